// round 5
// baseline (speedup 1.0000x reference)
#include <cuda_runtime.h>

// Problem constants
#define NNODE   10000
#define NEDGE   160000
#define FIN     3703
#define KPAD    3712     // FIN padded to multiple of 16
#define DMODEL  256
#define NHEAD   32
#define DK      16
#define QKV     512      // NHEAD*DK
#define QKV3    1536     // fused Q|K|V width
#define NLAYER  7

// GEMM tiling
#define BM 128
#define BN 128
#define SROW 20                    // 16 + 4 pad (conflict-free LDS)
#define TILE_F (128*SROW)          // 2560 floats per operand tile

#define SQ1 (QKV*DMODEL)           // 131072 (one layer of Wq)
#define SQT (NLAYER*SQ1)           // 917504
#define SOT (NLAYER*DMODEL*QKV)    // 917504
#define SMT (NLAYER*DMODEL*DMODEL) // 458752
#define WTOT (3*SQT + SOT + SMT)

// ---------------- device scratch ----------------
__device__ float g_xh [NNODE * KPAD];
__device__ float g_xl [NNODE * KPAD];
__device__ float g_Weh[DMODEL * KPAD];
__device__ float g_Wel[DMODEL * KPAD];
__device__ float g_Wfh[NLAYER * QKV3 * DMODEL];   // fused Wq|Wk|Wv hi
__device__ float g_Wfl[NLAYER * QKV3 * DMODEL];
__device__ float g_Woh[SOT];
__device__ float g_Wol[SOT];
__device__ float g_Wmh[SMT];
__device__ float g_Wml[SMT];

__device__ float g_h  [NNODE * DMODEL];
__device__ float g_hh [NNODE * DMODEL];
__device__ float g_hl [NNODE * DMODEL];
__device__ float g_t0 [NNODE * DMODEL];
__device__ float g_t1 [NNODE * DMODEL];
__device__ float g_t1h[NNODE * DMODEL];
__device__ float g_t1l[NNODE * DMODEL];
__device__ float g_QKV[NNODE * QKV3];
__device__ float g_ath[NNODE * QKV];
__device__ float g_atl[NNODE * QKV];

__device__ int g_cnt [NNODE];
__device__ int g_off [NNODE + 1];
__device__ int g_cur [NNODE];
__device__ int g_esrc[NEDGE];
__device__ int g_is64;

// ---------------- tf32 split ----------------
__device__ __forceinline__ void split1(float x, float& hi, float& lo) {
    unsigned h;
    asm("cvt.rna.tf32.f32 %0, %1;" : "=r"(h) : "f"(x));
    hi = __uint_as_float(h);
    float r = x - hi;
    unsigned l;
    asm("cvt.rna.tf32.f32 %0, %1;" : "=r"(l) : "f"(r));
    lo = __uint_as_float(l);
}

// ---------------- split kernels ----------------
__global__ void split_pad_kernel(const float* __restrict__ src,
                                 float* __restrict__ hi, float* __restrict__ lo,
                                 int cols, int colspad) {
    int row = blockIdx.x;
    const float* s = src + (size_t)row * cols;
    float* ph = hi + (size_t)row * colspad;
    float* pl = lo + (size_t)row * colspad;
    for (int c = threadIdx.x; c < cols; c += blockDim.x) {
        float h, l;
        split1(s[c], h, l);
        ph[c] = h; pl[c] = l;
    }
}

__global__ void splitw_kernel(const float* __restrict__ Wq, const float* __restrict__ Wk,
                              const float* __restrict__ Wv, const float* __restrict__ Wo,
                              const float* __restrict__ Wm) {
    int idx = blockIdx.x * blockDim.x + threadIdx.x;
    if (idx >= WTOT) return;
    float v; float *dh, *dl;
    if (idx < SQT) {
        int l = idx / SQ1, r = idx % SQ1;
        v = Wq[idx]; int d = l * (3 * SQ1) + r;
        dh = g_Wfh + d; dl = g_Wfl + d;
    } else if (idx < 2 * SQT) {
        int i2 = idx - SQT;
        int l = i2 / SQ1, r = i2 % SQ1;
        v = Wk[i2]; int d = l * (3 * SQ1) + SQ1 + r;
        dh = g_Wfh + d; dl = g_Wfl + d;
    } else if (idx < 3 * SQT) {
        int i2 = idx - 2 * SQT;
        int l = i2 / SQ1, r = i2 % SQ1;
        v = Wv[i2]; int d = l * (3 * SQ1) + 2 * SQ1 + r;
        dh = g_Wfh + d; dl = g_Wfl + d;
    } else if (idx < 3 * SQT + SOT) {
        int i2 = idx - 3 * SQT;
        v = Wo[i2]; dh = g_Woh + i2; dl = g_Wol + i2;
    } else {
        int i2 = idx - 3 * SQT - SOT;
        v = Wm[i2]; dh = g_Wmh + i2; dl = g_Wml + i2;
    }
    float h, l;
    split1(v, h, l);
    *dh = h; *dl = l;
}

// ---------------- edge index dtype detection + CSR ----------------
__global__ void detect_kernel(const unsigned int* __restrict__ w) {
    if (threadIdx.x == 0 && blockIdx.x == 0) {
        int is64 = 1;
        for (int i = 1; i < 128; i += 2)
            if (w[i] != 0u) { is64 = 0; break; }
        g_is64 = is64;
    }
}

__device__ __forceinline__ int read_edge(const void* eidx, int pos) {
    if (g_is64) return (int)(((const long long*)eidx)[pos]);
    return ((const int*)eidx)[pos];
}

__global__ void zero_cnt_kernel() {
    int i = blockIdx.x * blockDim.x + threadIdx.x;
    if (i < NNODE) g_cnt[i] = 0;
}

__global__ void hist_kernel(const void* __restrict__ eidx) {
    int e = blockIdx.x * blockDim.x + threadIdx.x;
    if (e >= NEDGE) return;
    atomicAdd(&g_cnt[read_edge(eidx, NEDGE + e)], 1);
}

__global__ void scan_kernel() {
    __shared__ int ss[1024];
    int t = threadIdx.x;
    const int CH = (NNODE + 1023) / 1024;
    int b = t * CH;
    int e = b + CH; if (e > NNODE) e = NNODE;
    int s = 0;
    for (int i = b; i < e; i++) s += g_cnt[i];
    ss[t] = s;
    __syncthreads();
    for (int o = 1; o < 1024; o <<= 1) {
        int v = (t >= o) ? ss[t - o] : 0;
        __syncthreads();
        ss[t] += v;
        __syncthreads();
    }
    int base = ss[t] - s;
    for (int i = b; i < e; i++) {
        g_off[i] = base;
        g_cur[i] = base;
        base += g_cnt[i];
    }
    if (t == 1023) g_off[NNODE] = ss[1023];
}

__global__ void scatter_kernel(const void* __restrict__ eidx) {
    int e = blockIdx.x * blockDim.x + threadIdx.x;
    if (e >= NEDGE) return;
    int d = read_edge(eidx, NEDGE + e);
    int s = read_edge(eidx, e);
    g_esrc[atomicAdd(&g_cur[d], 1)] = s;
}

// ---------------- mma helper ----------------
__device__ __forceinline__ void mma8(float* c,
                                     float a0, float a1, float a2, float a3,
                                     float b0, float b1) {
    asm volatile(
        "mma.sync.aligned.m16n8k8.row.col.f32.tf32.tf32.f32 "
        "{%0,%1,%2,%3}, {%4,%5,%6,%7}, {%8,%9}, {%0,%1,%2,%3};\n"
        : "+f"(c[0]), "+f"(c[1]), "+f"(c[2]), "+f"(c[3])
        : "r"(__float_as_uint(a0)), "r"(__float_as_uint(a1)),
          "r"(__float_as_uint(a2)), "r"(__float_as_uint(a3)),
          "r"(__float_as_uint(b0)), "r"(__float_as_uint(b1)));
}

// ---------------- GEMM: C = addend + bias + A @ B^T (3xTF32, pre-split) ----
// Virtual K' = 3K: seg0 Ah.Bh, seg1 Al.Bh, seg2 Ah.Bl. K multiple of 16.
// All global loads are clamped in-bounds; invalid rows are discarded at the
// epilogue (mma output rows are independent).
__global__ __launch_bounds__(256, 2)
void gemm3(const float* __restrict__ Ah, const float* __restrict__ Al,
           const float* __restrict__ Bh, const float* __restrict__ Bl,
           const float* __restrict__ bias, const float* __restrict__ addend,
           float* __restrict__ C, float* __restrict__ Ch, float* __restrict__ Cl,
           int M, int Nn, int K)
{
    __shared__ float smem[2][2 * TILE_F];   // 40 KB

    const int tid = threadIdx.x;
    const int m0 = blockIdx.y * BM;
    const int n0 = blockIdx.x * BN;
    const int lane = tid & 31, wid = tid >> 5;
    const int wm = wid & 1, wn = wid >> 1;
    const int g = lane >> 2, tg = lane & 3;

    const int nkt = K >> 4;
    const int T = 3 * nkt;

    float acc[4][4][4] = {};

    // per-thread load map: two (row, kcol) chunks covering 128 rows x 16 cols
    const int q0 = tid * 2, q1 = tid * 2 + 1;
    const int r0 = q0 >> 2, k0c = (q0 & 3) * 4;
    const int r1 = q1 >> 2, k1c = (q1 & 3) * 4;
    const int mA0 = (m0 + r0 < M) ? (m0 + r0) : (M - 1);
    const int mA1 = (m0 + r1 < M) ? (m0 + r1) : (M - 1);

    float4 ra[2], rb[2];

// NOTE: macro-internal names are underscore-prefixed and unique; the R3/R4
// IMA was `int t = (t_)` self-shadowing the caller's `t` at its own
// initializer (uninitialized read -> wild addresses).
#define LOADT(t_) do {                                                        \
        const int _lt  = (t_);                                                \
        const int _seg = (_lt >= nkt) + (_lt >= 2 * nkt);                     \
        const int _k16 = (_lt - _seg * nkt) << 4;                             \
        const float* _As = (_seg == 1) ? Al : Ah;                             \
        const float* _Bs = (_seg == 2) ? Bl : Bh;                             \
        ra[0] = *(const float4*)(_As + (size_t)mA0 * K + _k16 + k0c);         \
        ra[1] = *(const float4*)(_As + (size_t)mA1 * K + _k16 + k1c);         \
        rb[0] = *(const float4*)(_Bs + (size_t)(n0 + r0) * K + _k16 + k0c);   \
        rb[1] = *(const float4*)(_Bs + (size_t)(n0 + r1) * K + _k16 + k1c);   \
    } while (0)

#define STORET(st_) do {                                                      \
        float* _sA = smem[st_];                                               \
        float* _sB = _sA + TILE_F;                                            \
        *(float4*)&_sA[r0 * SROW + k0c] = ra[0];                              \
        *(float4*)&_sA[r1 * SROW + k1c] = ra[1];                              \
        *(float4*)&_sB[r0 * SROW + k0c] = rb[0];                              \
        *(float4*)&_sB[r1 * SROW + k1c] = rb[1];                              \
    } while (0)

    LOADT(0);
    STORET(0);
    __syncthreads();

    for (int t = 0; t < T; t++) {
        const int cur = t & 1;
        if (t + 1 < T) LOADT(t + 1);

        const float* sA = smem[cur];
        const float* sB = sA + TILE_F;
#pragma unroll
        for (int ks = 0; ks < 2; ks++) {
            const int kb = ks * 8;
            float b0[4], b1[4];
#pragma unroll
            for (int j = 0; j < 4; j++) {
                int rbx = (wn * 32 + j * 8 + g) * SROW + kb + tg;
                b0[j] = sB[rbx];
                b1[j] = sB[rbx + 4];
            }
#pragma unroll
            for (int i = 0; i < 4; i++) {
                int rax = (wm * 64 + i * 16 + g) * SROW + kb + tg;
                float a0 = sA[rax];
                float a1 = sA[rax + 8 * SROW];
                float a2 = sA[rax + 4];
                float a3 = sA[rax + 8 * SROW + 4];
#pragma unroll
                for (int j = 0; j < 4; j++)
                    mma8(acc[i][j], a0, a1, a2, a3, b0[j], b1[j]);
            }
        }

        if (t + 1 < T) STORET(cur ^ 1);
        __syncthreads();
    }
#undef LOADT
#undef STORET

    // epilogue
#pragma unroll
    for (int i = 0; i < 4; i++) {
        int mrow = m0 + wm * 64 + i * 16 + g;
#pragma unroll
        for (int j = 0; j < 4; j++) {
            int ncol = n0 + wn * 32 + j * 8 + tg * 2;
            float bv0 = 0.f, bv1 = 0.f;
            if (bias) { bv0 = bias[ncol]; bv1 = bias[ncol + 1]; }
#pragma unroll
            for (int r = 0; r < 2; r++) {
                int mr = mrow + r * 8;
                if (mr >= M) continue;
                size_t idx = (size_t)mr * Nn + ncol;
                float v0 = acc[i][j][r * 2 + 0] + bv0;
                float v1 = acc[i][j][r * 2 + 1] + bv1;
                if (addend) { v0 += addend[idx]; v1 += addend[idx + 1]; }
                C[idx]     = v0;
                C[idx + 1] = v1;
                if (Ch) {
                    float h0, l0, h1, l1;
                    split1(v0, h0, l0);
                    split1(v1, h1, l1);
                    Ch[idx] = h0;      Cl[idx] = l0;
                    Ch[idx + 1] = h1;  Cl[idx + 1] = l1;
                }
            }
        }
    }
}

// ---------------- LayerNorm (warp per row) with optional split outputs ----
__global__ __launch_bounds__(256)
void ln_kernel(const float* __restrict__ X, const float* __restrict__ gamma,
               const float* __restrict__ beta, float* __restrict__ Y,
               float* __restrict__ Yh, float* __restrict__ Yl)
{
    int idx = blockIdx.x * blockDim.x + threadIdx.x;
    int row = idx >> 5;
    int lane = idx & 31;
    if (row >= NNODE) return;

    const float4* xp = (const float4*)(X + (size_t)row * DMODEL);
    float4 v0 = xp[lane];
    float4 v1 = xp[lane + 32];

    float s = v0.x + v0.y + v0.z + v0.w + v1.x + v1.y + v1.z + v1.w;
#pragma unroll
    for (int o = 16; o; o >>= 1) s += __shfl_xor_sync(0xffffffffu, s, o);
    float mean = s * (1.f / 256.f);

    float d, q = 0.f;
    d = v0.x - mean; q += d * d;  d = v0.y - mean; q += d * d;
    d = v0.z - mean; q += d * d;  d = v0.w - mean; q += d * d;
    d = v1.x - mean; q += d * d;  d = v1.y - mean; q += d * d;
    d = v1.z - mean; q += d * d;  d = v1.w - mean; q += d * d;
#pragma unroll
    for (int o = 16; o; o >>= 1) q += __shfl_xor_sync(0xffffffffu, q, o);
    float inv = rsqrtf(q * (1.f / 256.f) + 1e-5f);

    const float4* gp = (const float4*)gamma;
    const float4* bp = (const float4*)beta;
    float4 g0 = gp[lane], g1 = gp[lane + 32];
    float4 b0 = bp[lane], b1 = bp[lane + 32];

    float4 o0, o1;
    o0.x = (v0.x - mean) * inv * g0.x + b0.x;
    o0.y = (v0.y - mean) * inv * g0.y + b0.y;
    o0.z = (v0.z - mean) * inv * g0.z + b0.z;
    o0.w = (v0.w - mean) * inv * g0.w + b0.w;
    o1.x = (v1.x - mean) * inv * g1.x + b1.x;
    o1.y = (v1.y - mean) * inv * g1.y + b1.y;
    o1.z = (v1.z - mean) * inv * g1.z + b1.z;
    o1.w = (v1.w - mean) * inv * g1.w + b1.w;

    float4* yp = (float4*)(Y + (size_t)row * DMODEL);
    yp[lane] = o0;
    yp[lane + 32] = o1;

    if (Yh) {
        float4 h0, l0, h1, l1;
        split1(o0.x, h0.x, l0.x); split1(o0.y, h0.y, l0.y);
        split1(o0.z, h0.z, l0.z); split1(o0.w, h0.w, l0.w);
        split1(o1.x, h1.x, l1.x); split1(o1.y, h1.y, l1.y);
        split1(o1.z, h1.z, l1.z); split1(o1.w, h1.w, l1.w);
        float4* hp = (float4*)(Yh + (size_t)row * DMODEL);
        float4* lp = (float4*)(Yl + (size_t)row * DMODEL);
        hp[lane] = h0;  hp[lane + 32] = h1;
        lp[lane] = l0;  lp[lane + 32] = l1;
    }
}

// ---------------- edge attention: warp/node, double-buffered K/V ----------
// QKVm rows of 1536: [Q(512) | K(512) | V(512)], per node, layout [head][elem].
__global__ __launch_bounds__(128)
void attn_kernel(const float* __restrict__ QKVm,
                 float* __restrict__ Omh, float* __restrict__ Oml)
{
    __shared__ float sm[4][512 + 2 * 1024];   // Q | (K0 V0) | (K1 V1)

    const int gwarp = (blockIdx.x * blockDim.x + threadIdx.x) >> 5;
    const int lane  = threadIdx.x & 31;
    const int winb  = threadIdx.x >> 5;
    if (gwarp >= NNODE) return;

    const int i = gwarp;
    const int a = lane >> 1;
    const int half = lane & 1;
    const int half2 = half * 2;

    float* Qs = &sm[winb][0];

    // load Q
    {
        const float4* qg = (const float4*)(QKVm + (size_t)i * QKV3);
        float4* qd = (float4*)Qs;
#pragma unroll
        for (int v = 0; v < 4; v++) qd[lane + 32 * v] = qg[lane + 32 * v];
    }

    float partial[32];
#pragma unroll
    for (int h = 0; h < 32; h++) partial[h] = 0.f;

    const int e0 = g_off[i];
    const int e1 = g_off[i + 1];

    float4 kr[4], vr[4];
    if (e0 < e1) {
        const float4* kg = (const float4*)(QKVm + (size_t)g_esrc[e0] * QKV3 + QKV);
        const float4* vg = kg + 128;
#pragma unroll
        for (int v = 0; v < 4; v++) { kr[v] = kg[lane + 32 * v]; vr[v] = vg[lane + 32 * v]; }
        float4* kd = (float4*)&sm[winb][512];
        float4* vd = (float4*)&sm[winb][1024];
#pragma unroll
        for (int v = 0; v < 4; v++) { kd[lane + 32 * v] = kr[v]; vd[lane + 32 * v] = vr[v]; }
    }
    __syncwarp();

    int cur = 0;
    for (int e = e0; e < e1; e++) {
        if (e + 1 < e1) {
            const float4* kg = (const float4*)(QKVm + (size_t)g_esrc[e + 1] * QKV3 + QKV);
            const float4* vg = kg + 128;
#pragma unroll
            for (int v = 0; v < 4; v++) { kr[v] = kg[lane + 32 * v]; vr[v] = vg[lane + 32 * v]; }
        }

        const float4* Ks4 = (const float4*)&sm[winb][512 + cur * 1024];
        const float4* Vs4 = Ks4 + 128;

        float acc[8];
#pragma unroll
        for (int b = 0; b < 8; b++) acc[b] = 0.f;
#pragma unroll
        for (int hh = 0; hh < 32; hh++) {
            float qa = Qs[hh * 16 + a];
            float4 k0 = Ks4[hh * 4 + half2];
            float4 k1 = Ks4[hh * 4 + half2 + 1];
            acc[0] += qa * k0.x; acc[1] += qa * k0.y;
            acc[2] += qa * k0.z; acc[3] += qa * k0.w;
            acc[4] += qa * k1.x; acc[5] += qa * k1.y;
            acc[6] += qa * k1.z; acc[7] += qa * k1.w;
        }
#pragma unroll
        for (int b = 0; b < 8; b++) acc[b] *= 0.25f;

        float mx = acc[0];
#pragma unroll
        for (int b = 1; b < 8; b++) mx = fmaxf(mx, acc[b]);
        mx = fmaxf(mx, __shfl_xor_sync(0xffffffffu, mx, 1));
        float ssum = 0.f;
#pragma unroll
        for (int b = 0; b < 8; b++) { acc[b] = __expf(acc[b] - mx); ssum += acc[b]; }
        ssum += __shfl_xor_sync(0xffffffffu, ssum, 1);
        float invs = 1.f / ssum;
#pragma unroll
        for (int b = 0; b < 8; b++) acc[b] *= invs;

#pragma unroll
        for (int hh = 0; hh < 32; hh++) {
            float4 v0 = Vs4[hh * 4 + half2];
            float4 v1 = Vs4[hh * 4 + half2 + 1];
            partial[hh] += acc[0] * v0.x + acc[1] * v0.y + acc[2] * v0.z + acc[3] * v0.w
                         + acc[4] * v1.x + acc[5] * v1.y + acc[6] * v1.z + acc[7] * v1.w;
        }

        if (e + 1 < e1) {
            float4* kd = (float4*)&sm[winb][512 + (cur ^ 1) * 1024];
            float4* vd = kd + 128;
#pragma unroll
            for (int v = 0; v < 4; v++) { kd[lane + 32 * v] = kr[v]; vd[lane + 32 * v] = vr[v]; }
        }
        __syncwarp();
        cur ^= 1;
    }

    float* oph = Omh + (size_t)i * QKV;
    float* opl = Oml + (size_t)i * QKV;
#pragma unroll
    for (int h = 0; h < 32; h++) {
        float tot = partial[h] + __shfl_xor_sync(0xffffffffu, partial[h], 1);
        if ((h >> 4) == half) {
            int idx = h * 16 + a;
            float th, tl;
            split1(tot, th, tl);
            oph[idx] = th;
            opl[idx] = tl;
        }
    }
}

// ---------------- host launcher ----------------
extern "C" void kernel_launch(void* const* d_in, const int* in_sizes, int n_in,
                              void* d_out, int out_size)
{
    const float* x       = (const float*)d_in[0];
    const void*  eidx    =               d_in[1];
    const float* W_embed = (const float*)d_in[2];
    const float* Wq      = (const float*)d_in[3];
    const float* Wk      = (const float*)d_in[4];
    const float* Wv      = (const float*)d_in[5];
    const float* Wo      = (const float*)d_in[6];
    const float* bo      = (const float*)d_in[7];
    const float* Wm      = (const float*)d_in[8];
    const float* bm      = (const float*)d_in[9];
    const float* g_ln    = (const float*)d_in[10];
    const float* b_ln    = (const float*)d_in[11];
    const float* g_mlp   = (const float*)d_in[12];
    const float* b_mlp   = (const float*)d_in[13];
    float* out = (float*)d_out;

    float *pxh, *pxl, *pWeh, *pWel, *pWfh, *pWfl, *pWoh, *pWol, *pWmh, *pWml;
    float *ph, *phh, *phl, *pt0, *pt1, *pt1h, *pt1l, *pQKV, *pAh, *pAl;
    cudaGetSymbolAddress((void**)&pxh,  g_xh);
    cudaGetSymbolAddress((void**)&pxl,  g_xl);
    cudaGetSymbolAddress((void**)&pWeh, g_Weh);
    cudaGetSymbolAddress((void**)&pWel, g_Wel);
    cudaGetSymbolAddress((void**)&pWfh, g_Wfh);
    cudaGetSymbolAddress((void**)&pWfl, g_Wfl);
    cudaGetSymbolAddress((void**)&pWoh, g_Woh);
    cudaGetSymbolAddress((void**)&pWol, g_Wol);
    cudaGetSymbolAddress((void**)&pWmh, g_Wmh);
    cudaGetSymbolAddress((void**)&pWml, g_Wml);
    cudaGetSymbolAddress((void**)&ph,   g_h);
    cudaGetSymbolAddress((void**)&phh,  g_hh);
    cudaGetSymbolAddress((void**)&phl,  g_hl);
    cudaGetSymbolAddress((void**)&pt0,  g_t0);
    cudaGetSymbolAddress((void**)&pt1,  g_t1);
    cudaGetSymbolAddress((void**)&pt1h, g_t1h);
    cudaGetSymbolAddress((void**)&pt1l, g_t1l);
    cudaGetSymbolAddress((void**)&pQKV, g_QKV);
    cudaGetSymbolAddress((void**)&pAh,  g_ath);
    cudaGetSymbolAddress((void**)&pAl,  g_atl);

    // 1-3: splits
    split_pad_kernel<<<NNODE, 256>>>(x, pxh, pxl, FIN, KPAD);
    split_pad_kernel<<<DMODEL, 256>>>(W_embed, pWeh, pWel, FIN, KPAD);
    splitw_kernel<<<(WTOT + 255) / 256, 256>>>(Wq, Wk, Wv, Wo, Wm);

    // 4-5: CSR part 1
    detect_kernel<<<1, 32>>>((const unsigned int*)eidx);
    zero_cnt_kernel<<<(NNODE + 255) / 256, 256>>>();

    // 6: embedding GEMM (ncu -s 5 captures this)
    const dim3 gEmb(DMODEL / BN, (NNODE + BM - 1) / BM);
    gemm3<<<gEmb, 256>>>(pxh, pxl, pWeh, pWel, nullptr, nullptr,
                         ph, phh, phl, NNODE, DMODEL, KPAD);

    // CSR part 2
    hist_kernel<<<(NEDGE + 255) / 256, 256>>>(eidx);
    scan_kernel<<<1, 1024>>>();
    scatter_kernel<<<(NEDGE + 255) / 256, 256>>>(eidx);

    const dim3 gF(QKV3 / BN,   (NNODE + BM - 1) / BM);   // 12 x 79
    const dim3 gD(DMODEL / BN, (NNODE + BM - 1) / BM);   // 2 x 79

    for (int l = 0; l < NLAYER; l++) {
        // fused QKV
        gemm3<<<gF, 256>>>(phh, phl,
                           pWfh + (size_t)l * QKV3 * DMODEL,
                           pWfl + (size_t)l * QKV3 * DMODEL,
                           nullptr, nullptr, pQKV, nullptr, nullptr,
                           NNODE, QKV3, DMODEL);

        attn_kernel<<<(NNODE + 3) / 4, 128>>>(pQKV, pAh, pAl);

        // h1x = h + attn @ Wo^T + bo
        gemm3<<<gD, 256>>>(pAh, pAl,
                           pWoh + (size_t)l * DMODEL * QKV,
                           pWol + (size_t)l * DMODEL * QKV,
                           bo + (size_t)l * DMODEL, ph,
                           pt0, nullptr, nullptr,
                           NNODE, DMODEL, QKV);
        ln_kernel<<<(NNODE * 32 + 255) / 256, 256>>>(pt0, g_ln + (size_t)l * DMODEL,
                                                     b_ln + (size_t)l * DMODEL,
                                                     pt1, pt1h, pt1l);

        // h2 = h1 + h1 @ Wm^T + bm
        gemm3<<<gD, 256>>>(pt1h, pt1l,
                           pWmh + (size_t)l * DMODEL * DMODEL,
                           pWml + (size_t)l * DMODEL * DMODEL,
                           bm + (size_t)l * DMODEL, pt1,
                           pt0, nullptr, nullptr,
                           NNODE, DMODEL, DMODEL);
        bool last = (l == NLAYER - 1);
        ln_kernel<<<(NNODE * 32 + 255) / 256, 256>>>(pt0, g_mlp + (size_t)l * DMODEL,
                                                     b_mlp + (size_t)l * DMODEL,
                                                     last ? out : ph,
                                                     last ? nullptr : phh,
                                                     last ? nullptr : phl);
    }
}

// round 6
// speedup vs baseline: 1.2156x; 1.2156x over previous
#include <cuda_runtime.h>

// Problem constants
#define NNODE   10000
#define NEDGE   160000
#define FIN     3703
#define KPAD    3712     // FIN padded to multiple of 16
#define DMODEL  256
#define NHEAD   32
#define DK      16
#define QKV     512      // NHEAD*DK
#define QKV3    1536     // fused Q|K|V width
#define NLAYER  7

// GEMM tiling (R2-proven skeleton: BK=16, double buffer, 96 mma/iter)
#define BM 128
#define BN 128
#define SROW 20                    // 16 + 4 pad (conflict-free LDS)
#define TILE_F (128*SROW)          // 2560 floats per tile
#define STAGE_F (4*TILE_F)         // Ah | Al | Bh | Bl
#define GEMM_SMEM_BYTES (2*STAGE_F*4)   // 81920, double buffered

#define SQ1 (QKV*DMODEL)           // 131072 (one layer of Wq)
#define SQT (NLAYER*SQ1)           // 917504
#define SOT (NLAYER*DMODEL*QKV)    // 917504
#define SMT (NLAYER*DMODEL*DMODEL) // 458752
#define WTOT (3*SQT + SOT + SMT)

// ---------------- device scratch ----------------
__device__ float g_xh [NNODE * KPAD];
__device__ float g_xl [NNODE * KPAD];
__device__ float g_Weh[DMODEL * KPAD];
__device__ float g_Wel[DMODEL * KPAD];
__device__ float g_Wfh[NLAYER * QKV3 * DMODEL];   // fused Wq|Wk|Wv hi
__device__ float g_Wfl[NLAYER * QKV3 * DMODEL];
__device__ float g_Woh[SOT];
__device__ float g_Wol[SOT];
__device__ float g_Wmh[SMT];
__device__ float g_Wml[SMT];

__device__ float g_h  [NNODE * DMODEL];
__device__ float g_hh [NNODE * DMODEL];
__device__ float g_hl [NNODE * DMODEL];
__device__ float g_t0 [NNODE * DMODEL];
__device__ float g_t1 [NNODE * DMODEL];
__device__ float g_t1h[NNODE * DMODEL];
__device__ float g_t1l[NNODE * DMODEL];
__device__ float g_QKV[NNODE * QKV3];
__device__ float g_ath[NNODE * QKV];
__device__ float g_atl[NNODE * QKV];

__device__ int g_cnt [NNODE];
__device__ int g_off [NNODE + 1];
__device__ int g_cur [NNODE];
__device__ int g_esrc[NEDGE];
__device__ int g_is64;

// ---------------- tf32 split ----------------
__device__ __forceinline__ void split1(float x, float& hi, float& lo) {
    unsigned h;
    asm("cvt.rna.tf32.f32 %0, %1;" : "=r"(h) : "f"(x));
    hi = __uint_as_float(h);
    float r = x - hi;
    unsigned l;
    asm("cvt.rna.tf32.f32 %0, %1;" : "=r"(l) : "f"(r));
    lo = __uint_as_float(l);
}

// ---------------- split kernels ----------------
__global__ void split_pad_kernel(const float* __restrict__ src,
                                 float* __restrict__ hi, float* __restrict__ lo,
                                 int cols, int colspad) {
    int row = blockIdx.x;
    const float* s = src + (size_t)row * cols;
    float* ph = hi + (size_t)row * colspad;
    float* pl = lo + (size_t)row * colspad;
    for (int c = threadIdx.x; c < cols; c += blockDim.x) {
        float h, l;
        split1(s[c], h, l);
        ph[c] = h; pl[c] = l;
    }
}

__global__ void splitw_kernel(const float* __restrict__ Wq, const float* __restrict__ Wk,
                              const float* __restrict__ Wv, const float* __restrict__ Wo,
                              const float* __restrict__ Wm) {
    int idx = blockIdx.x * blockDim.x + threadIdx.x;
    if (idx >= WTOT) return;
    float v; float *dh, *dl;
    if (idx < SQT) {
        int l = idx / SQ1, r = idx % SQ1;
        v = Wq[idx]; int d = l * (3 * SQ1) + r;
        dh = g_Wfh + d; dl = g_Wfl + d;
    } else if (idx < 2 * SQT) {
        int i2 = idx - SQT;
        int l = i2 / SQ1, r = i2 % SQ1;
        v = Wk[i2]; int d = l * (3 * SQ1) + SQ1 + r;
        dh = g_Wfh + d; dl = g_Wfl + d;
    } else if (idx < 3 * SQT) {
        int i2 = idx - 2 * SQT;
        int l = i2 / SQ1, r = i2 % SQ1;
        v = Wv[i2]; int d = l * (3 * SQ1) + 2 * SQ1 + r;
        dh = g_Wfh + d; dl = g_Wfl + d;
    } else if (idx < 3 * SQT + SOT) {
        int i2 = idx - 3 * SQT;
        v = Wo[i2]; dh = g_Woh + i2; dl = g_Wol + i2;
    } else {
        int i2 = idx - 3 * SQT - SOT;
        v = Wm[i2]; dh = g_Wmh + i2; dl = g_Wml + i2;
    }
    float h, l;
    split1(v, h, l);
    *dh = h; *dl = l;
}

// ---------------- edge index dtype detection + CSR ----------------
__global__ void detect_kernel(const unsigned int* __restrict__ w) {
    if (threadIdx.x == 0 && blockIdx.x == 0) {
        int is64 = 1;
        for (int i = 1; i < 128; i += 2)
            if (w[i] != 0u) { is64 = 0; break; }
        g_is64 = is64;
    }
}

__device__ __forceinline__ int read_edge(const void* eidx, int pos) {
    if (g_is64) return (int)(((const long long*)eidx)[pos]);
    return ((const int*)eidx)[pos];
}

__global__ void zero_cnt_kernel() {
    int i = blockIdx.x * blockDim.x + threadIdx.x;
    if (i < NNODE) g_cnt[i] = 0;
}

__global__ void hist_kernel(const void* __restrict__ eidx) {
    int e = blockIdx.x * blockDim.x + threadIdx.x;
    if (e >= NEDGE) return;
    atomicAdd(&g_cnt[read_edge(eidx, NEDGE + e)], 1);
}

__global__ void scan_kernel() {
    __shared__ int ss[1024];
    int t = threadIdx.x;
    const int CH = (NNODE + 1023) / 1024;
    int b = t * CH;
    int e = b + CH; if (e > NNODE) e = NNODE;
    int s = 0;
    for (int i = b; i < e; i++) s += g_cnt[i];
    ss[t] = s;
    __syncthreads();
    for (int o = 1; o < 1024; o <<= 1) {
        int v = (t >= o) ? ss[t - o] : 0;
        __syncthreads();
        ss[t] += v;
        __syncthreads();
    }
    int base = ss[t] - s;
    for (int i = b; i < e; i++) {
        g_off[i] = base;
        g_cur[i] = base;
        base += g_cnt[i];
    }
    if (t == 1023) g_off[NNODE] = ss[1023];
}

__global__ void scatter_kernel(const void* __restrict__ eidx) {
    int e = blockIdx.x * blockDim.x + threadIdx.x;
    if (e >= NEDGE) return;
    int d = read_edge(eidx, NEDGE + e);
    int s = read_edge(eidx, e);
    g_esrc[atomicAdd(&g_cur[d], 1)] = s;
}

// ---------------- mma helper ----------------
__device__ __forceinline__ void mma8(float* c,
                                     float a0, float a1, float a2, float a3,
                                     float b0, float b1) {
    asm volatile(
        "mma.sync.aligned.m16n8k8.row.col.f32.tf32.tf32.f32 "
        "{%0,%1,%2,%3}, {%4,%5,%6,%7}, {%8,%9}, {%0,%1,%2,%3};\n"
        : "+f"(c[0]), "+f"(c[1]), "+f"(c[2]), "+f"(c[3])
        : "r"(__float_as_uint(a0)), "r"(__float_as_uint(a1)),
          "r"(__float_as_uint(a2)), "r"(__float_as_uint(a3)),
          "r"(__float_as_uint(b0)), "r"(__float_as_uint(b1)));
}

// ---------------- GEMM: C = addend + bias + A @ B^T (3xTF32, pre-split) ----
// R2 skeleton: per k16 stage load Ah/Al/Bh/Bl tiles, 96 mma per stage.
// All global loads clamped in-bounds; invalid rows dropped in epilogue.
__global__ __launch_bounds__(256, 1)
void gemm3(const float* __restrict__ Ah, const float* __restrict__ Al,
           const float* __restrict__ Bh, const float* __restrict__ Bl,
           const float* __restrict__ bias, const float* __restrict__ addend,
           float* __restrict__ C, float* __restrict__ Ch, float* __restrict__ Cl,
           int M, int Nn, int K)
{
    extern __shared__ float smem[];

    const int tid = threadIdx.x;
    const int m0 = blockIdx.y * BM;
    const int n0 = blockIdx.x * BN;
    const int lane = tid & 31, wid = tid >> 5;
    const int wm = wid & 1, wn = wid >> 1;
    const int g = lane >> 2, tg = lane & 3;

    const int nkt = K >> 4;

    float acc[4][4][4] = {};

    // per-thread load map: two (row, kcol) chunks per tile
    const int q0 = tid * 2, q1 = tid * 2 + 1;
    const int r0 = q0 >> 2, k0c = (q0 & 3) * 4;
    const int r1 = q1 >> 2, k1c = (q1 & 3) * 4;
    const int mA0 = (m0 + r0 < M) ? (m0 + r0) : (M - 1);
    const int mA1 = (m0 + r1 < M) ? (m0 + r1) : (M - 1);

    float4 rah[2], ral[2], rbh[2], rbl[2];

#define LOADT(t_) do {                                                         \
        const int _k16 = (t_) << 4;                                           \
        rah[0] = *(const float4*)(Ah + (size_t)mA0 * K + _k16 + k0c);          \
        rah[1] = *(const float4*)(Ah + (size_t)mA1 * K + _k16 + k1c);          \
        ral[0] = *(const float4*)(Al + (size_t)mA0 * K + _k16 + k0c);          \
        ral[1] = *(const float4*)(Al + (size_t)mA1 * K + _k16 + k1c);          \
        rbh[0] = *(const float4*)(Bh + (size_t)(n0 + r0) * K + _k16 + k0c);    \
        rbh[1] = *(const float4*)(Bh + (size_t)(n0 + r1) * K + _k16 + k1c);    \
        rbl[0] = *(const float4*)(Bl + (size_t)(n0 + r0) * K + _k16 + k0c);    \
        rbl[1] = *(const float4*)(Bl + (size_t)(n0 + r1) * K + _k16 + k1c);    \
    } while (0)

#define STORET(st_) do {                                                       \
        float* _s = smem + (st_) * STAGE_F;                                    \
        *(float4*)&_s[              r0 * SROW + k0c] = rah[0];                 \
        *(float4*)&_s[              r1 * SROW + k1c] = rah[1];                 \
        *(float4*)&_s[TILE_F     +  r0 * SROW + k0c] = ral[0];                 \
        *(float4*)&_s[TILE_F     +  r1 * SROW + k1c] = ral[1];                 \
        *(float4*)&_s[2 * TILE_F +  r0 * SROW + k0c] = rbh[0];                 \
        *(float4*)&_s[2 * TILE_F +  r1 * SROW + k1c] = rbh[1];                 \
        *(float4*)&_s[3 * TILE_F +  r0 * SROW + k0c] = rbl[0];                 \
        *(float4*)&_s[3 * TILE_F +  r1 * SROW + k1c] = rbl[1];                 \
    } while (0)

    LOADT(0);
    STORET(0);
    __syncthreads();

    for (int t = 0; t < nkt; t++) {
        const int cur = t & 1;
        if (t + 1 < nkt) LOADT(t + 1);

        const float* sAh = smem + cur * STAGE_F;
        const float* sAl = sAh + TILE_F;
        const float* sBh = sAh + 2 * TILE_F;
        const float* sBl = sAh + 3 * TILE_F;

#pragma unroll
        for (int ks = 0; ks < 2; ks++) {
            const int kb = ks * 8;
            float bh[4][2], bl[4][2];
#pragma unroll
            for (int j = 0; j < 4; j++) {
                int rbx = (wn * 32 + j * 8 + g) * SROW + kb + tg;
                bh[j][0] = sBh[rbx];  bh[j][1] = sBh[rbx + 4];
                bl[j][0] = sBl[rbx];  bl[j][1] = sBl[rbx + 4];
            }
#pragma unroll
            for (int i = 0; i < 4; i++) {
                int rax = (wm * 64 + i * 16 + g) * SROW + kb + tg;
                float ah0 = sAh[rax];
                float ah1 = sAh[rax + 8 * SROW];
                float ah2 = sAh[rax + 4];
                float ah3 = sAh[rax + 8 * SROW + 4];
                float al0 = sAl[rax];
                float al1 = sAl[rax + 8 * SROW];
                float al2 = sAl[rax + 4];
                float al3 = sAl[rax + 8 * SROW + 4];
#pragma unroll
                for (int j = 0; j < 4; j++) {
                    mma8(acc[i][j], ah0, ah1, ah2, ah3, bh[j][0], bh[j][1]);
                    mma8(acc[i][j], al0, al1, al2, al3, bh[j][0], bh[j][1]);
                    mma8(acc[i][j], ah0, ah1, ah2, ah3, bl[j][0], bl[j][1]);
                }
            }
        }

        if (t + 1 < nkt) STORET(cur ^ 1);
        __syncthreads();
    }
#undef LOADT
#undef STORET

    // epilogue
#pragma unroll
    for (int i = 0; i < 4; i++) {
        int mrow = m0 + wm * 64 + i * 16 + g;
#pragma unroll
        for (int j = 0; j < 4; j++) {
            int ncol = n0 + wn * 32 + j * 8 + tg * 2;
            float bv0 = 0.f, bv1 = 0.f;
            if (bias) { bv0 = bias[ncol]; bv1 = bias[ncol + 1]; }
#pragma unroll
            for (int r = 0; r < 2; r++) {
                int mr = mrow + r * 8;
                if (mr >= M) continue;
                size_t idx = (size_t)mr * Nn + ncol;
                float v0 = acc[i][j][r * 2 + 0] + bv0;
                float v1 = acc[i][j][r * 2 + 1] + bv1;
                if (addend) { v0 += addend[idx]; v1 += addend[idx + 1]; }
                C[idx]     = v0;
                C[idx + 1] = v1;
                if (Ch) {
                    float h0, l0, h1, l1;
                    split1(v0, h0, l0);
                    split1(v1, h1, l1);
                    Ch[idx] = h0;      Cl[idx] = l0;
                    Ch[idx + 1] = h1;  Cl[idx + 1] = l1;
                }
            }
        }
    }
}

// ---------------- LayerNorm (warp per row) with optional split outputs ----
__global__ __launch_bounds__(256)
void ln_kernel(const float* __restrict__ X, const float* __restrict__ gamma,
               const float* __restrict__ beta, float* __restrict__ Y,
               float* __restrict__ Yh, float* __restrict__ Yl)
{
    int idx = blockIdx.x * blockDim.x + threadIdx.x;
    int row = idx >> 5;
    int lane = idx & 31;
    if (row >= NNODE) return;

    const float4* xp = (const float4*)(X + (size_t)row * DMODEL);
    float4 v0 = xp[lane];
    float4 v1 = xp[lane + 32];

    float s = v0.x + v0.y + v0.z + v0.w + v1.x + v1.y + v1.z + v1.w;
#pragma unroll
    for (int o = 16; o; o >>= 1) s += __shfl_xor_sync(0xffffffffu, s, o);
    float mean = s * (1.f / 256.f);

    float d, q = 0.f;
    d = v0.x - mean; q += d * d;  d = v0.y - mean; q += d * d;
    d = v0.z - mean; q += d * d;  d = v0.w - mean; q += d * d;
    d = v1.x - mean; q += d * d;  d = v1.y - mean; q += d * d;
    d = v1.z - mean; q += d * d;  d = v1.w - mean; q += d * d;
#pragma unroll
    for (int o = 16; o; o >>= 1) q += __shfl_xor_sync(0xffffffffu, q, o);
    float inv = rsqrtf(q * (1.f / 256.f) + 1e-5f);

    const float4* gp = (const float4*)gamma;
    const float4* bp = (const float4*)beta;
    float4 g0 = gp[lane], g1 = gp[lane + 32];
    float4 b0 = bp[lane], b1 = bp[lane + 32];

    float4 o0, o1;
    o0.x = (v0.x - mean) * inv * g0.x + b0.x;
    o0.y = (v0.y - mean) * inv * g0.y + b0.y;
    o0.z = (v0.z - mean) * inv * g0.z + b0.z;
    o0.w = (v0.w - mean) * inv * g0.w + b0.w;
    o1.x = (v1.x - mean) * inv * g1.x + b1.x;
    o1.y = (v1.y - mean) * inv * g1.y + b1.y;
    o1.z = (v1.z - mean) * inv * g1.z + b1.z;
    o1.w = (v1.w - mean) * inv * g1.w + b1.w;

    float4* yp = (float4*)(Y + (size_t)row * DMODEL);
    yp[lane] = o0;
    yp[lane + 32] = o1;

    if (Yh) {
        float4 h0, l0, h1, l1;
        split1(o0.x, h0.x, l0.x); split1(o0.y, h0.y, l0.y);
        split1(o0.z, h0.z, l0.z); split1(o0.w, h0.w, l0.w);
        split1(o1.x, h1.x, l1.x); split1(o1.y, h1.y, l1.y);
        split1(o1.z, h1.z, l1.z); split1(o1.w, h1.w, l1.w);
        float4* hp = (float4*)(Yh + (size_t)row * DMODEL);
        float4* lp = (float4*)(Yl + (size_t)row * DMODEL);
        hp[lane] = h0;  hp[lane + 32] = h1;
        lp[lane] = l0;  lp[lane + 32] = l1;
    }
}

// ---------------- edge attention: warp/node, double-buffered K/V ----------
// QKVm rows of 1536: [Q(512) | K(512) | V(512)], per node, layout [head][elem].
__global__ __launch_bounds__(128)
void attn_kernel(const float* __restrict__ QKVm,
                 float* __restrict__ Omh, float* __restrict__ Oml)
{
    __shared__ float sm[4][512 + 2 * 1024];   // Q | (K0 V0) | (K1 V1)

    const int gwarp = (blockIdx.x * blockDim.x + threadIdx.x) >> 5;
    const int lane  = threadIdx.x & 31;
    const int winb  = threadIdx.x >> 5;
    if (gwarp >= NNODE) return;

    const int i = gwarp;
    const int a = lane >> 1;
    const int half = lane & 1;
    const int half2 = half * 2;

    float* Qs = &sm[winb][0];

    // load Q
    {
        const float4* qg = (const float4*)(QKVm + (size_t)i * QKV3);
        float4* qd = (float4*)Qs;
#pragma unroll
        for (int v = 0; v < 4; v++) qd[lane + 32 * v] = qg[lane + 32 * v];
    }

    float partial[32];
#pragma unroll
    for (int h = 0; h < 32; h++) partial[h] = 0.f;

    const int e0 = g_off[i];
    const int e1 = g_off[i + 1];

    float4 kr[4], vr[4];
    if (e0 < e1) {
        const float4* kg = (const float4*)(QKVm + (size_t)g_esrc[e0] * QKV3 + QKV);
        const float4* vg = kg + 128;
#pragma unroll
        for (int v = 0; v < 4; v++) { kr[v] = kg[lane + 32 * v]; vr[v] = vg[lane + 32 * v]; }
        float4* kd = (float4*)&sm[winb][512];
        float4* vd = (float4*)&sm[winb][1024];
#pragma unroll
        for (int v = 0; v < 4; v++) { kd[lane + 32 * v] = kr[v]; vd[lane + 32 * v] = vr[v]; }
    }
    __syncwarp();

    int cur = 0;
    for (int e = e0; e < e1; e++) {
        if (e + 1 < e1) {
            const float4* kg = (const float4*)(QKVm + (size_t)g_esrc[e + 1] * QKV3 + QKV);
            const float4* vg = kg + 128;
#pragma unroll
            for (int v = 0; v < 4; v++) { kr[v] = kg[lane + 32 * v]; vr[v] = vg[lane + 32 * v]; }
        }

        const float4* Ks4 = (const float4*)&sm[winb][512 + cur * 1024];
        const float4* Vs4 = Ks4 + 128;

        float acc[8];
#pragma unroll
        for (int b = 0; b < 8; b++) acc[b] = 0.f;
#pragma unroll
        for (int hh = 0; hh < 32; hh++) {
            float qa = Qs[hh * 16 + a];
            float4 k0 = Ks4[hh * 4 + half2];
            float4 k1 = Ks4[hh * 4 + half2 + 1];
            acc[0] += qa * k0.x; acc[1] += qa * k0.y;
            acc[2] += qa * k0.z; acc[3] += qa * k0.w;
            acc[4] += qa * k1.x; acc[5] += qa * k1.y;
            acc[6] += qa * k1.z; acc[7] += qa * k1.w;
        }
#pragma unroll
        for (int b = 0; b < 8; b++) acc[b] *= 0.25f;

        float mx = acc[0];
#pragma unroll
        for (int b = 1; b < 8; b++) mx = fmaxf(mx, acc[b]);
        mx = fmaxf(mx, __shfl_xor_sync(0xffffffffu, mx, 1));
        float ssum = 0.f;
#pragma unroll
        for (int b = 0; b < 8; b++) { acc[b] = __expf(acc[b] - mx); ssum += acc[b]; }
        ssum += __shfl_xor_sync(0xffffffffu, ssum, 1);
        float invs = 1.f / ssum;
#pragma unroll
        for (int b = 0; b < 8; b++) acc[b] *= invs;

#pragma unroll
        for (int hh = 0; hh < 32; hh++) {
            float4 v0 = Vs4[hh * 4 + half2];
            float4 v1 = Vs4[hh * 4 + half2 + 1];
            partial[hh] += acc[0] * v0.x + acc[1] * v0.y + acc[2] * v0.z + acc[3] * v0.w
                         + acc[4] * v1.x + acc[5] * v1.y + acc[6] * v1.z + acc[7] * v1.w;
        }

        if (e + 1 < e1) {
            float4* kd = (float4*)&sm[winb][512 + (cur ^ 1) * 1024];
            float4* vd = kd + 128;
#pragma unroll
            for (int v = 0; v < 4; v++) { kd[lane + 32 * v] = kr[v]; vd[lane + 32 * v] = vr[v]; }
        }
        __syncwarp();
        cur ^= 1;
    }

    float* oph = Omh + (size_t)i * QKV;
    float* opl = Oml + (size_t)i * QKV;
#pragma unroll
    for (int h = 0; h < 32; h++) {
        float tot = partial[h] + __shfl_xor_sync(0xffffffffu, partial[h], 1);
        if ((h >> 4) == half) {
            int idx = h * 16 + a;
            float th, tl;
            split1(tot, th, tl);
            oph[idx] = th;
            opl[idx] = tl;
        }
    }
}

// ---------------- host launcher ----------------
extern "C" void kernel_launch(void* const* d_in, const int* in_sizes, int n_in,
                              void* d_out, int out_size)
{
    const float* x       = (const float*)d_in[0];
    const void*  eidx    =               d_in[1];
    const float* W_embed = (const float*)d_in[2];
    const float* Wq      = (const float*)d_in[3];
    const float* Wk      = (const float*)d_in[4];
    const float* Wv      = (const float*)d_in[5];
    const float* Wo      = (const float*)d_in[6];
    const float* bo      = (const float*)d_in[7];
    const float* Wm      = (const float*)d_in[8];
    const float* bm      = (const float*)d_in[9];
    const float* g_ln    = (const float*)d_in[10];
    const float* b_ln    = (const float*)d_in[11];
    const float* g_mlp   = (const float*)d_in[12];
    const float* b_mlp   = (const float*)d_in[13];
    float* out = (float*)d_out;

    float *pxh, *pxl, *pWeh, *pWel, *pWfh, *pWfl, *pWoh, *pWol, *pWmh, *pWml;
    float *ph, *phh, *phl, *pt0, *pt1, *pt1h, *pt1l, *pQKV, *pAh, *pAl;
    cudaGetSymbolAddress((void**)&pxh,  g_xh);
    cudaGetSymbolAddress((void**)&pxl,  g_xl);
    cudaGetSymbolAddress((void**)&pWeh, g_Weh);
    cudaGetSymbolAddress((void**)&pWel, g_Wel);
    cudaGetSymbolAddress((void**)&pWfh, g_Wfh);
    cudaGetSymbolAddress((void**)&pWfl, g_Wfl);
    cudaGetSymbolAddress((void**)&pWoh, g_Woh);
    cudaGetSymbolAddress((void**)&pWol, g_Wol);
    cudaGetSymbolAddress((void**)&pWmh, g_Wmh);
    cudaGetSymbolAddress((void**)&pWml, g_Wml);
    cudaGetSymbolAddress((void**)&ph,   g_h);
    cudaGetSymbolAddress((void**)&phh,  g_hh);
    cudaGetSymbolAddress((void**)&phl,  g_hl);
    cudaGetSymbolAddress((void**)&pt0,  g_t0);
    cudaGetSymbolAddress((void**)&pt1,  g_t1);
    cudaGetSymbolAddress((void**)&pt1h, g_t1h);
    cudaGetSymbolAddress((void**)&pt1l, g_t1l);
    cudaGetSymbolAddress((void**)&pQKV, g_QKV);
    cudaGetSymbolAddress((void**)&pAh,  g_ath);
    cudaGetSymbolAddress((void**)&pAl,  g_atl);

    cudaFuncSetAttribute(gemm3, cudaFuncAttributeMaxDynamicSharedMemorySize,
                         GEMM_SMEM_BYTES);

    // launches 1-3: splits
    split_pad_kernel<<<NNODE, 256>>>(x, pxh, pxl, FIN, KPAD);
    split_pad_kernel<<<DMODEL, 256>>>(W_embed, pWeh, pWel, FIN, KPAD);
    splitw_kernel<<<(WTOT + 255) / 256, 256>>>(Wq, Wk, Wv, Wo, Wm);

    // launch 4: embedding GEMM (profiler captures launch #4)
    const dim3 gEmb(DMODEL / BN, (NNODE + BM - 1) / BM);
    gemm3<<<gEmb, 256, GEMM_SMEM_BYTES>>>(pxh, pxl, pWeh, pWel, nullptr, nullptr,
                                          ph, phh, phl, NNODE, DMODEL, KPAD);

    // CSR build
    detect_kernel<<<1, 32>>>((const unsigned int*)eidx);
    zero_cnt_kernel<<<(NNODE + 255) / 256, 256>>>();
    hist_kernel<<<(NEDGE + 255) / 256, 256>>>(eidx);
    scan_kernel<<<1, 1024>>>();
    scatter_kernel<<<(NEDGE + 255) / 256, 256>>>(eidx);

    const dim3 gF(QKV3 / BN,   (NNODE + BM - 1) / BM);   // 12 x 79
    const dim3 gD(DMODEL / BN, (NNODE + BM - 1) / BM);   // 2 x 79

    for (int l = 0; l < NLAYER; l++) {
        // fused QKV
        gemm3<<<gF, 256, GEMM_SMEM_BYTES>>>(phh, phl,
                                            pWfh + (size_t)l * QKV3 * DMODEL,
                                            pWfl + (size_t)l * QKV3 * DMODEL,
                                            nullptr, nullptr, pQKV, nullptr, nullptr,
                                            NNODE, QKV3, DMODEL);

        attn_kernel<<<(NNODE + 3) / 4, 128>>>(pQKV, pAh, pAl);

        // h1x = h + attn @ Wo^T + bo
        gemm3<<<gD, 256, GEMM_SMEM_BYTES>>>(pAh, pAl,
                                            pWoh + (size_t)l * DMODEL * QKV,
                                            pWol + (size_t)l * DMODEL * QKV,
                                            bo + (size_t)l * DMODEL, ph,
                                            pt0, nullptr, nullptr,
                                            NNODE, DMODEL, QKV);
        ln_kernel<<<(NNODE * 32 + 255) / 256, 256>>>(pt0, g_ln + (size_t)l * DMODEL,
                                                     b_ln + (size_t)l * DMODEL,
                                                     pt1, pt1h, pt1l);

        // h2 = h1 + h1 @ Wm^T + bm
        gemm3<<<gD, 256, GEMM_SMEM_BYTES>>>(pt1h, pt1l,
                                            pWmh + (size_t)l * DMODEL * DMODEL,
                                            pWml + (size_t)l * DMODEL * DMODEL,
                                            bm + (size_t)l * DMODEL, pt1,
                                            pt0, nullptr, nullptr,
                                            NNODE, DMODEL, DMODEL);
        bool last = (l == NLAYER - 1);
        ln_kernel<<<(NNODE * 32 + 255) / 256, 256>>>(pt0, g_mlp + (size_t)l * DMODEL,
                                                     b_mlp + (size_t)l * DMODEL,
                                                     last ? out : ph,
                                                     last ? nullptr : phh,
                                                     last ? nullptr : phl);
    }
}

// round 7
// speedup vs baseline: 1.6937x; 1.3933x over previous
#include <cuda_runtime.h>
#include <cuda_fp16.h>

// Problem constants
#define NNODE   10000
#define NEDGE   160000
#define FIN     3703
#define KPAD    3712     // FIN padded to multiple of 16
#define DMODEL  256
#define NHEAD   32
#define DK      16
#define QKV     512      // NHEAD*DK
#define QKV3    1536     // fused Q|K|V width
#define NLAYER  7

// GEMM tiling (fp16 3-term, double buffer)
#define BM 128
#define BN 128
#define SROWH 24                   // 16 halves + 8 pad (48B rows, conflict-free)
#define TILE_H (128*SROWH)         // 3072 halves per tile
#define STAGE_H (4*TILE_H)         // Ah | Al | Bh | Bl = 24KB
#define WSCALE 32.0f
#define WINV   0.03125f

#define SQ1 (QKV*DMODEL)           // 131072 (one layer of Wq)
#define SQT (NLAYER*SQ1)           // 917504
#define SOT (NLAYER*DMODEL*QKV)    // 917504
#define SMT (NLAYER*DMODEL*DMODEL) // 458752
#define WTOT (3*SQT + SOT + SMT)

// ---------------- device scratch ----------------
__device__ __half g_xh [NNODE * KPAD];
__device__ __half g_xl [NNODE * KPAD];
__device__ __half g_Weh[DMODEL * KPAD];
__device__ __half g_Wel[DMODEL * KPAD];
__device__ __half g_Wfh[NLAYER * QKV3 * DMODEL];   // fused Wq|Wk|Wv (x32)
__device__ __half g_Wfl[NLAYER * QKV3 * DMODEL];
__device__ __half g_Woh[SOT];
__device__ __half g_Wol[SOT];
__device__ __half g_Wmh[SMT];
__device__ __half g_Wml[SMT];

__device__ float  g_h  [NNODE * DMODEL];
__device__ __half g_hh [NNODE * DMODEL];
__device__ __half g_hl [NNODE * DMODEL];
__device__ float  g_t0 [NNODE * DMODEL];
__device__ float  g_t1 [NNODE * DMODEL];
__device__ __half g_t1h[NNODE * DMODEL];
__device__ __half g_t1l[NNODE * DMODEL];
__device__ float  g_QKV[NNODE * QKV3];
__device__ __half g_ath[NNODE * QKV];
__device__ __half g_atl[NNODE * QKV];

__device__ int g_cnt [NNODE];
__device__ int g_off [NNODE + 1];
__device__ int g_cur [NNODE];
__device__ int g_esrc[NEDGE];
__device__ int g_is64;

// ---------------- fp16 two-term split ----------------
__device__ __forceinline__ void splith(float x, __half& hi, __half& lo) {
    hi = __float2half_rn(x);
    lo = __float2half_rn(x - __half2float(hi));
}

// ---------------- split kernels ----------------
__global__ void split_pad_kernel(const float* __restrict__ src,
                                 __half* __restrict__ hi, __half* __restrict__ lo,
                                 int cols, int colspad, float scale) {
    int row = blockIdx.x;
    const float* s = src + (size_t)row * cols;
    __half* ph = hi + (size_t)row * colspad;
    __half* pl = lo + (size_t)row * colspad;
    for (int c = threadIdx.x; c < cols; c += blockDim.x) {
        __half h, l;
        splith(s[c] * scale, h, l);
        ph[c] = h; pl[c] = l;
    }
}

__global__ void splitw_kernel(const float* __restrict__ Wq, const float* __restrict__ Wk,
                              const float* __restrict__ Wv, const float* __restrict__ Wo,
                              const float* __restrict__ Wm) {
    int idx = blockIdx.x * blockDim.x + threadIdx.x;
    if (idx >= WTOT) return;
    float v; __half *dh, *dl;
    if (idx < SQT) {
        int l = idx / SQ1, r = idx % SQ1;
        v = Wq[idx]; int d = l * (3 * SQ1) + r;
        dh = g_Wfh + d; dl = g_Wfl + d;
    } else if (idx < 2 * SQT) {
        int i2 = idx - SQT;
        int l = i2 / SQ1, r = i2 % SQ1;
        v = Wk[i2]; int d = l * (3 * SQ1) + SQ1 + r;
        dh = g_Wfh + d; dl = g_Wfl + d;
    } else if (idx < 3 * SQT) {
        int i2 = idx - 2 * SQT;
        int l = i2 / SQ1, r = i2 % SQ1;
        v = Wv[i2]; int d = l * (3 * SQ1) + 2 * SQ1 + r;
        dh = g_Wfh + d; dl = g_Wfl + d;
    } else if (idx < 3 * SQT + SOT) {
        int i2 = idx - 3 * SQT;
        v = Wo[i2]; dh = g_Woh + i2; dl = g_Wol + i2;
    } else {
        int i2 = idx - 3 * SQT - SOT;
        v = Wm[i2]; dh = g_Wmh + i2; dl = g_Wml + i2;
    }
    __half h, l;
    splith(v * WSCALE, h, l);
    *dh = h; *dl = l;
}

// ---------------- edge index dtype detection + CSR ----------------
__global__ void detect_kernel(const unsigned int* __restrict__ w) {
    if (threadIdx.x == 0 && blockIdx.x == 0) {
        int is64 = 1;
        for (int i = 1; i < 128; i += 2)
            if (w[i] != 0u) { is64 = 0; break; }
        g_is64 = is64;
    }
}

__device__ __forceinline__ int read_edge(const void* eidx, int pos) {
    if (g_is64) return (int)(((const long long*)eidx)[pos]);
    return ((const int*)eidx)[pos];
}

__global__ void zero_cnt_kernel() {
    int i = blockIdx.x * blockDim.x + threadIdx.x;
    if (i < NNODE) g_cnt[i] = 0;
}

__global__ void hist_kernel(const void* __restrict__ eidx) {
    int e = blockIdx.x * blockDim.x + threadIdx.x;
    if (e >= NEDGE) return;
    atomicAdd(&g_cnt[read_edge(eidx, NEDGE + e)], 1);
}

__global__ void scan_kernel() {
    __shared__ int ss[1024];
    int t = threadIdx.x;
    const int CH = (NNODE + 1023) / 1024;
    int b = t * CH;
    int e = b + CH; if (e > NNODE) e = NNODE;
    int s = 0;
    for (int i = b; i < e; i++) s += g_cnt[i];
    ss[t] = s;
    __syncthreads();
    for (int o = 1; o < 1024; o <<= 1) {
        int v = (t >= o) ? ss[t - o] : 0;
        __syncthreads();
        ss[t] += v;
        __syncthreads();
    }
    int base = ss[t] - s;
    for (int i = b; i < e; i++) {
        g_off[i] = base;
        g_cur[i] = base;
        base += g_cnt[i];
    }
    if (t == 1023) g_off[NNODE] = ss[1023];
}

__global__ void scatter_kernel(const void* __restrict__ eidx) {
    int e = blockIdx.x * blockDim.x + threadIdx.x;
    if (e >= NEDGE) return;
    int d = read_edge(eidx, NEDGE + e);
    int s = read_edge(eidx, e);
    g_esrc[atomicAdd(&g_cur[d], 1)] = s;
}

// ---------------- fp16 mma helper (m16n8k16) ----------------
__device__ __forceinline__ void mma16(float* c,
                                      unsigned a0, unsigned a1, unsigned a2, unsigned a3,
                                      unsigned b0, unsigned b1) {
    asm volatile(
        "mma.sync.aligned.m16n8k16.row.col.f32.f16.f16.f32 "
        "{%0,%1,%2,%3}, {%4,%5,%6,%7}, {%8,%9}, {%0,%1,%2,%3};\n"
        : "+f"(c[0]), "+f"(c[1]), "+f"(c[2]), "+f"(c[3])
        : "r"(a0), "r"(a1), "r"(a2), "r"(a3), "r"(b0), "r"(b1));
}

// ---------------- GEMM: C = addend + bias + (A @ B^T)/32  (3xFP16) --------
// A = Ah+Al (unscaled), B = Bh+Bl (pre-scaled x32). Terms: AhBh + AlBh + AhBl.
// K multiple of 16. Loads clamped in-bounds; invalid rows dropped in epilogue.
__global__ __launch_bounds__(256, 2)
void gemm3h(const __half* __restrict__ Ah, const __half* __restrict__ Al,
            const __half* __restrict__ Bh, const __half* __restrict__ Bl,
            const float* __restrict__ bias, const float* __restrict__ addend,
            float* __restrict__ C, __half* __restrict__ Ch, __half* __restrict__ Cl,
            int M, int Nn, int K)
{
    __shared__ __align__(16) __half smem[2][STAGE_H];   // 48 KB

    const int tid = threadIdx.x;
    const int m0 = blockIdx.y * BM;
    const int n0 = blockIdx.x * BN;
    const int lane = tid & 31, wid = tid >> 5;
    const int wm = wid & 1, wn = wid >> 1;
    const int g = lane >> 2, tg = lane & 3;

    const int nkt = K >> 4;

    float acc[4][4][4] = {};

    // load map: one uint4 (8 halves) per tile per thread
    const int lr = tid >> 1;            // row 0..127
    const int lc = (tid & 1) * 8;       // half-col 0 or 8
    const int mA = (m0 + lr < M) ? (m0 + lr) : (M - 1);
    const int nB = n0 + lr;             // Nn multiple of 128

    uint4 vah, val, vbh, vbl;

#define LOADT(t_) do {                                                         \
        const int _k16 = (t_) << 4;                                           \
        vah = *(const uint4*)(Ah + (size_t)mA * K + _k16 + lc);                \
        val = *(const uint4*)(Al + (size_t)mA * K + _k16 + lc);                \
        vbh = *(const uint4*)(Bh + (size_t)nB * K + _k16 + lc);                \
        vbl = *(const uint4*)(Bl + (size_t)nB * K + _k16 + lc);                \
    } while (0)

#define STORET(st_) do {                                                       \
        __half* _s = smem[st_];                                                \
        *(uint4*)&_s[             lr * SROWH + lc] = vah;                      \
        *(uint4*)&_s[TILE_H     + lr * SROWH + lc] = val;                      \
        *(uint4*)&_s[2 * TILE_H + lr * SROWH + lc] = vbh;                      \
        *(uint4*)&_s[3 * TILE_H + lr * SROWH + lc] = vbl;                      \
    } while (0)

    LOADT(0);
    STORET(0);
    __syncthreads();

    for (int t = 0; t < nkt; t++) {
        const int cur = t & 1;
        if (t + 1 < nkt) LOADT(t + 1);

        const __half* sAh = smem[cur];
        const __half* sAl = sAh + TILE_H;
        const __half* sBh = sAh + 2 * TILE_H;
        const __half* sBl = sAh + 3 * TILE_H;

        unsigned bh0[4], bh1[4], bl0[4], bl1[4];
#pragma unroll
        for (int j = 0; j < 4; j++) {
            int rbx = (wn * 32 + j * 8 + g) * SROWH + 2 * tg;
            bh0[j] = *(const unsigned*)&sBh[rbx];
            bh1[j] = *(const unsigned*)&sBh[rbx + 8];
            bl0[j] = *(const unsigned*)&sBl[rbx];
            bl1[j] = *(const unsigned*)&sBl[rbx + 8];
        }
#pragma unroll
        for (int i = 0; i < 4; i++) {
            int rax = (wm * 64 + i * 16 + g) * SROWH + 2 * tg;
            unsigned ah0 = *(const unsigned*)&sAh[rax];
            unsigned ah1 = *(const unsigned*)&sAh[rax + 8 * SROWH];
            unsigned ah2 = *(const unsigned*)&sAh[rax + 8];
            unsigned ah3 = *(const unsigned*)&sAh[rax + 8 * SROWH + 8];
            unsigned al0 = *(const unsigned*)&sAl[rax];
            unsigned al1 = *(const unsigned*)&sAl[rax + 8 * SROWH];
            unsigned al2 = *(const unsigned*)&sAl[rax + 8];
            unsigned al3 = *(const unsigned*)&sAl[rax + 8 * SROWH + 8];
#pragma unroll
            for (int j = 0; j < 4; j++) {
                mma16(acc[i][j], ah0, ah1, ah2, ah3, bh0[j], bh1[j]);
                mma16(acc[i][j], al0, al1, al2, al3, bh0[j], bh1[j]);
                mma16(acc[i][j], ah0, ah1, ah2, ah3, bl0[j], bl1[j]);
            }
        }

        if (t + 1 < nkt) STORET(cur ^ 1);
        __syncthreads();
    }
#undef LOADT
#undef STORET

    // epilogue: rescale by 1/32 (weights were pre-scaled x32)
#pragma unroll
    for (int i = 0; i < 4; i++) {
        int mrow = m0 + wm * 64 + i * 16 + g;
#pragma unroll
        for (int j = 0; j < 4; j++) {
            int ncol = n0 + wn * 32 + j * 8 + tg * 2;
            float bv0 = 0.f, bv1 = 0.f;
            if (bias) { bv0 = bias[ncol]; bv1 = bias[ncol + 1]; }
#pragma unroll
            for (int r = 0; r < 2; r++) {
                int mr = mrow + r * 8;
                if (mr >= M) continue;
                size_t idx = (size_t)mr * Nn + ncol;
                float v0 = acc[i][j][r * 2 + 0] * WINV + bv0;
                float v1 = acc[i][j][r * 2 + 1] * WINV + bv1;
                if (addend) { v0 += addend[idx]; v1 += addend[idx + 1]; }
                C[idx]     = v0;
                C[idx + 1] = v1;
                if (Ch) {
                    __half h0, l0, h1, l1;
                    splith(v0, h0, l0);
                    splith(v1, h1, l1);
                    Ch[idx] = h0;      Cl[idx] = l0;
                    Ch[idx + 1] = h1;  Cl[idx + 1] = l1;
                }
            }
        }
    }
}

// ---------------- LayerNorm (warp per row) with optional split outputs ----
__global__ __launch_bounds__(256)
void ln_kernel(const float* __restrict__ X, const float* __restrict__ gamma,
               const float* __restrict__ beta, float* __restrict__ Y,
               __half* __restrict__ Yh, __half* __restrict__ Yl)
{
    int idx = blockIdx.x * blockDim.x + threadIdx.x;
    int row = idx >> 5;
    int lane = idx & 31;
    if (row >= NNODE) return;

    const float4* xp = (const float4*)(X + (size_t)row * DMODEL);
    float4 v0 = xp[lane];
    float4 v1 = xp[lane + 32];

    float s = v0.x + v0.y + v0.z + v0.w + v1.x + v1.y + v1.z + v1.w;
#pragma unroll
    for (int o = 16; o; o >>= 1) s += __shfl_xor_sync(0xffffffffu, s, o);
    float mean = s * (1.f / 256.f);

    float d, q = 0.f;
    d = v0.x - mean; q += d * d;  d = v0.y - mean; q += d * d;
    d = v0.z - mean; q += d * d;  d = v0.w - mean; q += d * d;
    d = v1.x - mean; q += d * d;  d = v1.y - mean; q += d * d;
    d = v1.z - mean; q += d * d;  d = v1.w - mean; q += d * d;
#pragma unroll
    for (int o = 16; o; o >>= 1) q += __shfl_xor_sync(0xffffffffu, q, o);
    float inv = rsqrtf(q * (1.f / 256.f) + 1e-5f);

    const float4* gp = (const float4*)gamma;
    const float4* bp = (const float4*)beta;
    float4 g0 = gp[lane], g1 = gp[lane + 32];
    float4 b0 = bp[lane], b1 = bp[lane + 32];

    float o0[4], o1[4];
    o0[0] = (v0.x - mean) * inv * g0.x + b0.x;
    o0[1] = (v0.y - mean) * inv * g0.y + b0.y;
    o0[2] = (v0.z - mean) * inv * g0.z + b0.z;
    o0[3] = (v0.w - mean) * inv * g0.w + b0.w;
    o1[0] = (v1.x - mean) * inv * g1.x + b1.x;
    o1[1] = (v1.y - mean) * inv * g1.y + b1.y;
    o1[2] = (v1.z - mean) * inv * g1.z + b1.z;
    o1[3] = (v1.w - mean) * inv * g1.w + b1.w;

    float4* yp = (float4*)(Y + (size_t)row * DMODEL);
    yp[lane]      = make_float4(o0[0], o0[1], o0[2], o0[3]);
    yp[lane + 32] = make_float4(o1[0], o1[1], o1[2], o1[3]);

    if (Yh) {
        __half hbuf0[4], lbuf0[4], hbuf1[4], lbuf1[4];
#pragma unroll
        for (int k = 0; k < 4; k++) {
            splith(o0[k], hbuf0[k], lbuf0[k]);
            splith(o1[k], hbuf1[k], lbuf1[k]);
        }
        // 4 halves = 8B = uint2
        uint2* hp = (uint2*)(Yh + (size_t)row * DMODEL);
        uint2* lp = (uint2*)(Yl + (size_t)row * DMODEL);
        hp[lane]      = *(uint2*)hbuf0;
        hp[lane + 32] = *(uint2*)hbuf1;
        lp[lane]      = *(uint2*)lbuf0;
        lp[lane + 32] = *(uint2*)lbuf1;
    }
}

// ---------------- edge attention: warp/node, double-buffered K/V ----------
// QKVm rows of 1536: [Q(512) | K(512) | V(512)], per node, layout [head][elem].
__global__ __launch_bounds__(128)
void attn_kernel(const float* __restrict__ QKVm,
                 __half* __restrict__ Omh, __half* __restrict__ Oml)
{
    __shared__ float sm[4][512 + 2 * 1024];   // Q | (K0 V0) | (K1 V1)

    const int gwarp = (blockIdx.x * blockDim.x + threadIdx.x) >> 5;
    const int lane  = threadIdx.x & 31;
    const int winb  = threadIdx.x >> 5;
    if (gwarp >= NNODE) return;

    const int i = gwarp;
    const int a = lane >> 1;
    const int half = lane & 1;
    const int half2 = half * 2;

    float* Qs = &sm[winb][0];

    // load Q
    {
        const float4* qg = (const float4*)(QKVm + (size_t)i * QKV3);
        float4* qd = (float4*)Qs;
#pragma unroll
        for (int v = 0; v < 4; v++) qd[lane + 32 * v] = qg[lane + 32 * v];
    }

    float partial[32];
#pragma unroll
    for (int h = 0; h < 32; h++) partial[h] = 0.f;

    const int e0 = g_off[i];
    const int e1 = g_off[i + 1];

    float4 kr[4], vr[4];
    if (e0 < e1) {
        const float4* kg = (const float4*)(QKVm + (size_t)g_esrc[e0] * QKV3 + QKV);
        const float4* vg = kg + 128;
#pragma unroll
        for (int v = 0; v < 4; v++) { kr[v] = kg[lane + 32 * v]; vr[v] = vg[lane + 32 * v]; }
        float4* kd = (float4*)&sm[winb][512];
        float4* vd = (float4*)&sm[winb][1024];
#pragma unroll
        for (int v = 0; v < 4; v++) { kd[lane + 32 * v] = kr[v]; vd[lane + 32 * v] = vr[v]; }
    }
    __syncwarp();

    int cur = 0;
    for (int e = e0; e < e1; e++) {
        if (e + 1 < e1) {
            const float4* kg = (const float4*)(QKVm + (size_t)g_esrc[e + 1] * QKV3 + QKV);
            const float4* vg = kg + 128;
#pragma unroll
            for (int v = 0; v < 4; v++) { kr[v] = kg[lane + 32 * v]; vr[v] = vg[lane + 32 * v]; }
        }

        const float4* Ks4 = (const float4*)&sm[winb][512 + cur * 1024];
        const float4* Vs4 = Ks4 + 128;

        float acc[8];
#pragma unroll
        for (int b = 0; b < 8; b++) acc[b] = 0.f;
#pragma unroll
        for (int hh = 0; hh < 32; hh++) {
            float qa = Qs[hh * 16 + a];
            float4 k0 = Ks4[hh * 4 + half2];
            float4 k1 = Ks4[hh * 4 + half2 + 1];
            acc[0] += qa * k0.x; acc[1] += qa * k0.y;
            acc[2] += qa * k0.z; acc[3] += qa * k0.w;
            acc[4] += qa * k1.x; acc[5] += qa * k1.y;
            acc[6] += qa * k1.z; acc[7] += qa * k1.w;
        }
#pragma unroll
        for (int b = 0; b < 8; b++) acc[b] *= 0.25f;

        float mx = acc[0];
#pragma unroll
        for (int b = 1; b < 8; b++) mx = fmaxf(mx, acc[b]);
        mx = fmaxf(mx, __shfl_xor_sync(0xffffffffu, mx, 1));
        float ssum = 0.f;
#pragma unroll
        for (int b = 0; b < 8; b++) { acc[b] = __expf(acc[b] - mx); ssum += acc[b]; }
        ssum += __shfl_xor_sync(0xffffffffu, ssum, 1);
        float invs = 1.f / ssum;
#pragma unroll
        for (int b = 0; b < 8; b++) acc[b] *= invs;

#pragma unroll
        for (int hh = 0; hh < 32; hh++) {
            float4 v0 = Vs4[hh * 4 + half2];
            float4 v1 = Vs4[hh * 4 + half2 + 1];
            partial[hh] += acc[0] * v0.x + acc[1] * v0.y + acc[2] * v0.z + acc[3] * v0.w
                         + acc[4] * v1.x + acc[5] * v1.y + acc[6] * v1.z + acc[7] * v1.w;
        }

        if (e + 1 < e1) {
            float4* kd = (float4*)&sm[winb][512 + (cur ^ 1) * 1024];
            float4* vd = kd + 128;
#pragma unroll
            for (int v = 0; v < 4; v++) { kd[lane + 32 * v] = kr[v]; vd[lane + 32 * v] = vr[v]; }
        }
        __syncwarp();
        cur ^= 1;
    }

    __half* oph = Omh + (size_t)i * QKV;
    __half* opl = Oml + (size_t)i * QKV;
#pragma unroll
    for (int h = 0; h < 32; h++) {
        float tot = partial[h] + __shfl_xor_sync(0xffffffffu, partial[h], 1);
        if ((h >> 4) == half) {
            int idx = h * 16 + a;
            __half th, tl;
            splith(tot, th, tl);
            oph[idx] = th;
            opl[idx] = tl;
        }
    }
}

// ---------------- host launcher ----------------
extern "C" void kernel_launch(void* const* d_in, const int* in_sizes, int n_in,
                              void* d_out, int out_size)
{
    const float* x       = (const float*)d_in[0];
    const void*  eidx    =               d_in[1];
    const float* W_embed = (const float*)d_in[2];
    const float* Wq      = (const float*)d_in[3];
    const float* Wk      = (const float*)d_in[4];
    const float* Wv      = (const float*)d_in[5];
    const float* Wo      = (const float*)d_in[6];
    const float* bo      = (const float*)d_in[7];
    const float* Wm      = (const float*)d_in[8];
    const float* bm      = (const float*)d_in[9];
    const float* g_ln    = (const float*)d_in[10];
    const float* b_ln    = (const float*)d_in[11];
    const float* g_mlp   = (const float*)d_in[12];
    const float* b_mlp   = (const float*)d_in[13];
    float* out = (float*)d_out;

    __half *pxh, *pxl, *pWeh, *pWel, *pWfh, *pWfl, *pWoh, *pWol, *pWmh, *pWml;
    __half *phh, *phl, *pt1h, *pt1l, *pAh, *pAl;
    float *ph, *pt0, *pt1, *pQKV;
    cudaGetSymbolAddress((void**)&pxh,  g_xh);
    cudaGetSymbolAddress((void**)&pxl,  g_xl);
    cudaGetSymbolAddress((void**)&pWeh, g_Weh);
    cudaGetSymbolAddress((void**)&pWel, g_Wel);
    cudaGetSymbolAddress((void**)&pWfh, g_Wfh);
    cudaGetSymbolAddress((void**)&pWfl, g_Wfl);
    cudaGetSymbolAddress((void**)&pWoh, g_Woh);
    cudaGetSymbolAddress((void**)&pWol, g_Wol);
    cudaGetSymbolAddress((void**)&pWmh, g_Wmh);
    cudaGetSymbolAddress((void**)&pWml, g_Wml);
    cudaGetSymbolAddress((void**)&ph,   g_h);
    cudaGetSymbolAddress((void**)&phh,  g_hh);
    cudaGetSymbolAddress((void**)&phl,  g_hl);
    cudaGetSymbolAddress((void**)&pt0,  g_t0);
    cudaGetSymbolAddress((void**)&pt1,  g_t1);
    cudaGetSymbolAddress((void**)&pt1h, g_t1h);
    cudaGetSymbolAddress((void**)&pt1l, g_t1l);
    cudaGetSymbolAddress((void**)&pQKV, g_QKV);
    cudaGetSymbolAddress((void**)&pAh,  g_ath);
    cudaGetSymbolAddress((void**)&pAl,  g_atl);

    // launches 1-3: splits (x unscaled; all weights x32)
    split_pad_kernel<<<NNODE, 256>>>(x, pxh, pxl, FIN, KPAD, 1.0f);
    split_pad_kernel<<<DMODEL, 256>>>(W_embed, pWeh, pWel, FIN, KPAD, WSCALE);
    splitw_kernel<<<(WTOT + 255) / 256, 256>>>(Wq, Wk, Wv, Wo, Wm);

    // launch 4: embedding GEMM (profiler captures launch #4)
    const dim3 gEmb(DMODEL / BN, (NNODE + BM - 1) / BM);
    gemm3h<<<gEmb, 256>>>(pxh, pxl, pWeh, pWel, nullptr, nullptr,
                          ph, phh, phl, NNODE, DMODEL, KPAD);

    // CSR build
    detect_kernel<<<1, 32>>>((const unsigned int*)eidx);
    zero_cnt_kernel<<<(NNODE + 255) / 256, 256>>>();
    hist_kernel<<<(NEDGE + 255) / 256, 256>>>(eidx);
    scan_kernel<<<1, 1024>>>();
    scatter_kernel<<<(NEDGE + 255) / 256, 256>>>(eidx);

    const dim3 gF(QKV3 / BN,   (NNODE + BM - 1) / BM);   // 12 x 79
    const dim3 gD(DMODEL / BN, (NNODE + BM - 1) / BM);   // 2 x 79

    for (int l = 0; l < NLAYER; l++) {
        // fused QKV
        gemm3h<<<gF, 256>>>(phh, phl,
                            pWfh + (size_t)l * QKV3 * DMODEL,
                            pWfl + (size_t)l * QKV3 * DMODEL,
                            nullptr, nullptr, pQKV, nullptr, nullptr,
                            NNODE, QKV3, DMODEL);

        attn_kernel<<<(NNODE + 3) / 4, 128>>>(pQKV, pAh, pAl);

        // h1x = h + attn @ Wo^T + bo
        gemm3h<<<gD, 256>>>(pAh, pAl,
                            pWoh + (size_t)l * DMODEL * QKV,
                            pWol + (size_t)l * DMODEL * QKV,
                            bo + (size_t)l * DMODEL, ph,
                            pt0, nullptr, nullptr,
                            NNODE, DMODEL, QKV);
        ln_kernel<<<(NNODE * 32 + 255) / 256, 256>>>(pt0, g_ln + (size_t)l * DMODEL,
                                                     b_ln + (size_t)l * DMODEL,
                                                     pt1, pt1h, pt1l);

        // h2 = h1 + h1 @ Wm^T + bm
        gemm3h<<<gD, 256>>>(pt1h, pt1l,
                            pWmh + (size_t)l * DMODEL * DMODEL,
                            pWml + (size_t)l * DMODEL * DMODEL,
                            bm + (size_t)l * DMODEL, pt1,
                            pt0, nullptr, nullptr,
                            NNODE, DMODEL, DMODEL);
        bool last = (l == NLAYER - 1);
        ln_kernel<<<(NNODE * 32 + 255) / 256, 256>>>(pt0, g_mlp + (size_t)l * DMODEL,
                                                     b_mlp + (size_t)l * DMODEL,
                                                     last ? out : ph,
                                                     last ? nullptr : phh,
                                                     last ? nullptr : phl);
    }
}

// round 8
// speedup vs baseline: 1.7730x; 1.0468x over previous
#include <cuda_runtime.h>
#include <cuda_fp16.h>

// Problem constants
#define NNODE   10000
#define NEDGE   160000
#define FIN     3703
#define KPAD    3712     // FIN padded to multiple of 16
#define DMODEL  256
#define NHEAD   32
#define DK      16
#define QKV     512      // NHEAD*DK
#define QKV3    1536     // fused Q|K|V width
#define NLAYER  7

// GEMM tiling (fp16 3-term, double buffer)
#define BM 128
#define BN 128
#define SROWH 24                   // 16 halves + 8 pad (48B rows, LDSM conflict-free)
#define TILE_H (128*SROWH)         // 3072 halves per tile
#define STAGE_H (4*TILE_H)         // Ah | Al | Bh | Bl = 24KB
#define WSCALE 32.0f
#define WINV   0.03125f

#define SQ1 (QKV*DMODEL)           // 131072 (one layer of Wq)
#define SQT (NLAYER*SQ1)           // 917504
#define SOT (NLAYER*DMODEL*QKV)    // 917504
#define SMT (NLAYER*DMODEL*DMODEL) // 458752
#define WTOT (3*SQT + SOT + SMT)

// ---------------- device scratch ----------------
__device__ __half g_xh [NNODE * KPAD];
__device__ __half g_xl [NNODE * KPAD];
__device__ __half g_Weh[DMODEL * KPAD];
__device__ __half g_Wel[DMODEL * KPAD];
__device__ __half g_Wfh[NLAYER * QKV3 * DMODEL];   // fused Wq|Wk|Wv (x32)
__device__ __half g_Wfl[NLAYER * QKV3 * DMODEL];
__device__ __half g_Woh[SOT];
__device__ __half g_Wol[SOT];
__device__ __half g_Wmh[SMT];
__device__ __half g_Wml[SMT];

__device__ float  g_h  [NNODE * DMODEL];
__device__ __half g_hh [NNODE * DMODEL];
__device__ __half g_hl [NNODE * DMODEL];
__device__ float  g_t0 [NNODE * DMODEL];
__device__ float  g_t1 [NNODE * DMODEL];
__device__ __half g_t1h[NNODE * DMODEL];
__device__ __half g_t1l[NNODE * DMODEL];
__device__ float  g_QKV[NNODE * QKV3];
__device__ __half g_ath[NNODE * QKV];
__device__ __half g_atl[NNODE * QKV];

__device__ int g_cnt [NNODE];
__device__ int g_off [NNODE + 1];
__device__ int g_cur [NNODE];
__device__ int g_esrc[NEDGE];
__device__ int g_is64;

// ---------------- fp16 two-term split ----------------
__device__ __forceinline__ void splith(float x, __half& hi, __half& lo) {
    hi = __float2half_rn(x);
    lo = __float2half_rn(x - __half2float(hi));
}

// ---------------- split kernels ----------------
__global__ void split_pad_kernel(const float* __restrict__ src,
                                 __half* __restrict__ hi, __half* __restrict__ lo,
                                 int cols, int colspad, float scale) {
    int row = blockIdx.x;
    const float* s = src + (size_t)row * cols;
    __half* ph = hi + (size_t)row * colspad;
    __half* pl = lo + (size_t)row * colspad;
    for (int c = threadIdx.x; c < cols; c += blockDim.x) {
        __half h, l;
        splith(s[c] * scale, h, l);
        ph[c] = h; pl[c] = l;
    }
}

__global__ void splitw_kernel(const float* __restrict__ Wq, const float* __restrict__ Wk,
                              const float* __restrict__ Wv, const float* __restrict__ Wo,
                              const float* __restrict__ Wm) {
    int idx = blockIdx.x * blockDim.x + threadIdx.x;
    if (idx >= WTOT) return;
    float v; __half *dh, *dl;
    if (idx < SQT) {
        int l = idx / SQ1, r = idx % SQ1;
        v = Wq[idx]; int d = l * (3 * SQ1) + r;
        dh = g_Wfh + d; dl = g_Wfl + d;
    } else if (idx < 2 * SQT) {
        int i2 = idx - SQT;
        int l = i2 / SQ1, r = i2 % SQ1;
        v = Wk[i2]; int d = l * (3 * SQ1) + SQ1 + r;
        dh = g_Wfh + d; dl = g_Wfl + d;
    } else if (idx < 3 * SQT) {
        int i2 = idx - 2 * SQT;
        int l = i2 / SQ1, r = i2 % SQ1;
        v = Wv[i2]; int d = l * (3 * SQ1) + 2 * SQ1 + r;
        dh = g_Wfh + d; dl = g_Wfl + d;
    } else if (idx < 3 * SQT + SOT) {
        int i2 = idx - 3 * SQT;
        v = Wo[i2]; dh = g_Woh + i2; dl = g_Wol + i2;
    } else {
        int i2 = idx - 3 * SQT - SOT;
        v = Wm[i2]; dh = g_Wmh + i2; dl = g_Wml + i2;
    }
    __half h, l;
    splith(v * WSCALE, h, l);
    *dh = h; *dl = l;
}

// ---------------- edge index dtype detection + CSR ----------------
__global__ void detect_kernel(const unsigned int* __restrict__ w) {
    if (threadIdx.x == 0 && blockIdx.x == 0) {
        int is64 = 1;
        for (int i = 1; i < 128; i += 2)
            if (w[i] != 0u) { is64 = 0; break; }
        g_is64 = is64;
    }
}

__device__ __forceinline__ int read_edge(const void* eidx, int pos) {
    if (g_is64) return (int)(((const long long*)eidx)[pos]);
    return ((const int*)eidx)[pos];
}

__global__ void zero_cnt_kernel() {
    int i = blockIdx.x * blockDim.x + threadIdx.x;
    if (i < NNODE) g_cnt[i] = 0;
}

__global__ void hist_kernel(const void* __restrict__ eidx) {
    int e = blockIdx.x * blockDim.x + threadIdx.x;
    if (e >= NEDGE) return;
    atomicAdd(&g_cnt[read_edge(eidx, NEDGE + e)], 1);
}

__global__ void scan_kernel() {
    __shared__ int ss[1024];
    int t = threadIdx.x;
    const int CH = (NNODE + 1023) / 1024;
    int b = t * CH;
    int e = b + CH; if (e > NNODE) e = NNODE;
    int s = 0;
    for (int i = b; i < e; i++) s += g_cnt[i];
    ss[t] = s;
    __syncthreads();
    for (int o = 1; o < 1024; o <<= 1) {
        int v = (t >= o) ? ss[t - o] : 0;
        __syncthreads();
        ss[t] += v;
        __syncthreads();
    }
    int base = ss[t] - s;
    for (int i = b; i < e; i++) {
        g_off[i] = base;
        g_cur[i] = base;
        base += g_cnt[i];
    }
    if (t == 1023) g_off[NNODE] = ss[1023];
}

__global__ void scatter_kernel(const void* __restrict__ eidx) {
    int e = blockIdx.x * blockDim.x + threadIdx.x;
    if (e >= NEDGE) return;
    int d = read_edge(eidx, NEDGE + e);
    int s = read_edge(eidx, e);
    g_esrc[atomicAdd(&g_cur[d], 1)] = s;
}

// ---------------- fp16 mma + ldmatrix helpers ----------------
__device__ __forceinline__ void mma16(float* c,
                                      unsigned a0, unsigned a1, unsigned a2, unsigned a3,
                                      unsigned b0, unsigned b1) {
    asm volatile(
        "mma.sync.aligned.m16n8k16.row.col.f32.f16.f16.f32 "
        "{%0,%1,%2,%3}, {%4,%5,%6,%7}, {%8,%9}, {%0,%1,%2,%3};\n"
        : "+f"(c[0]), "+f"(c[1]), "+f"(c[2]), "+f"(c[3])
        : "r"(a0), "r"(a1), "r"(a2), "r"(a3), "r"(b0), "r"(b1));
}

__device__ __forceinline__ void ldsm4(unsigned& r0, unsigned& r1,
                                      unsigned& r2, unsigned& r3, unsigned addr) {
    asm volatile(
        "ldmatrix.sync.aligned.m8n8.x4.shared.b16 {%0,%1,%2,%3}, [%4];\n"
        : "=r"(r0), "=r"(r1), "=r"(r2), "=r"(r3) : "r"(addr));
}

// ---------------- GEMM: C = addend + bias + (A @ B^T)/32  (3xFP16) --------
// A = Ah+Al (unscaled), B = Bh+Bl (pre-scaled x32). Terms: AhBh + AlBh + AhBl.
// Fragments loaded via ldmatrix.x4 from padded (48B-stride) smem rows.
__global__ __launch_bounds__(256, 2)
void gemm3h(const __half* __restrict__ Ah, const __half* __restrict__ Al,
            const __half* __restrict__ Bh, const __half* __restrict__ Bl,
            const float* __restrict__ bias, const float* __restrict__ addend,
            float* __restrict__ C, __half* __restrict__ Ch, __half* __restrict__ Cl,
            int M, int Nn, int K)
{
    __shared__ __align__(16) __half smem[2][STAGE_H];   // 48 KB

    const int tid = threadIdx.x;
    const int m0 = blockIdx.y * BM;
    const int n0 = blockIdx.x * BN;
    const int lane = tid & 31, wid = tid >> 5;
    const int wm = wid & 1, wn = wid >> 1;
    const int g = lane >> 2, tg = lane & 3;

    const int nkt = K >> 4;

    float acc[4][4][4] = {};

    // global->smem load map: one uint4 (8 halves) per tile per thread
    const int lr = tid >> 1;            // row 0..127
    const int lc = (tid & 1) * 8;       // half-col 0 or 8
    const int mA = (m0 + lr < M) ? (m0 + lr) : (M - 1);
    const int nB = n0 + lr;             // Nn multiple of 128

    // ldmatrix per-lane offsets (bytes, within a tile)
    // A x4: mat0(r0-7,k0-7) mat1(r8-15,k0-7) mat2(r0-7,k8-15) mat3(r8-15,k8-15)
    const int a_row = ((lane >> 3) & 1) * 8 + (lane & 7);
    const int a_col = ((lane >> 4) & 1) * 8;
    const unsigned aoffB = (unsigned)((a_row * SROWH + a_col) * 2);
    // B x4 (j-pair): mat0(j0,k0-7) mat1(j0,k8-15) mat2(j1,k0-7) mat3(j1,k8-15)
    const int b_row = ((lane >> 4) & 1) * 8 + (lane & 7);
    const int b_col = ((lane >> 3) & 1) * 8;
    const unsigned boffB = (unsigned)((b_row * SROWH + b_col) * 2);

    unsigned sbase[2];
    sbase[0] = (unsigned)__cvta_generic_to_shared(&smem[0][0]);
    sbase[1] = (unsigned)__cvta_generic_to_shared(&smem[1][0]);

    uint4 vah, val, vbh, vbl;

#define LOADT(t_) do {                                                         \
        const int _k16 = (t_) << 4;                                           \
        vah = *(const uint4*)(Ah + (size_t)mA * K + _k16 + lc);                \
        val = *(const uint4*)(Al + (size_t)mA * K + _k16 + lc);                \
        vbh = *(const uint4*)(Bh + (size_t)nB * K + _k16 + lc);                \
        vbl = *(const uint4*)(Bl + (size_t)nB * K + _k16 + lc);                \
    } while (0)

#define STORET(st_) do {                                                       \
        __half* _s = smem[st_];                                                \
        *(uint4*)&_s[             lr * SROWH + lc] = vah;                      \
        *(uint4*)&_s[TILE_H     + lr * SROWH + lc] = val;                      \
        *(uint4*)&_s[2 * TILE_H + lr * SROWH + lc] = vbh;                      \
        *(uint4*)&_s[3 * TILE_H + lr * SROWH + lc] = vbl;                      \
    } while (0)

    LOADT(0);
    STORET(0);
    __syncthreads();

    for (int t = 0; t < nkt; t++) {
        const int cur = t & 1;
        if (t + 1 < nkt) LOADT(t + 1);

        const unsigned sb = sbase[cur];

        // B fragments: 2 ldmatrix.x4 per hi/lo (j-pairs {0,1} and {2,3})
        unsigned bh0[4], bh1[4], bl0[4], bl1[4];
#pragma unroll
        for (int jp = 0; jp < 2; jp++) {
            unsigned bd = sb + (unsigned)((2 * TILE_H + (wn * 32 + jp * 16) * SROWH) * 2) + boffB;
            ldsm4(bh0[2 * jp], bh1[2 * jp], bh0[2 * jp + 1], bh1[2 * jp + 1], bd);
            ldsm4(bl0[2 * jp], bl1[2 * jp], bl0[2 * jp + 1], bl1[2 * jp + 1],
                  bd + (unsigned)(TILE_H * 2));
        }
#pragma unroll
        for (int i = 0; i < 4; i++) {
            unsigned ad = sb + (unsigned)(((wm * 64 + i * 16) * SROWH) * 2) + aoffB;
            unsigned ah0, ah1, ah2, ah3, al0, al1, al2, al3;
            ldsm4(ah0, ah1, ah2, ah3, ad);
            ldsm4(al0, al1, al2, al3, ad + (unsigned)(TILE_H * 2));
#pragma unroll
            for (int j = 0; j < 4; j++) {
                mma16(acc[i][j], ah0, ah1, ah2, ah3, bh0[j], bh1[j]);
                mma16(acc[i][j], al0, al1, al2, al3, bh0[j], bh1[j]);
                mma16(acc[i][j], ah0, ah1, ah2, ah3, bl0[j], bl1[j]);
            }
        }

        if (t + 1 < nkt) STORET(cur ^ 1);
        __syncthreads();
    }
#undef LOADT
#undef STORET

    (void)g; (void)tg;

    // epilogue: rescale by 1/32 (weights were pre-scaled x32)
#pragma unroll
    for (int i = 0; i < 4; i++) {
        int mrow = m0 + wm * 64 + i * 16 + (lane >> 2);
#pragma unroll
        for (int j = 0; j < 4; j++) {
            int ncol = n0 + wn * 32 + j * 8 + (lane & 3) * 2;
            float bv0 = 0.f, bv1 = 0.f;
            if (bias) { bv0 = bias[ncol]; bv1 = bias[ncol + 1]; }
#pragma unroll
            for (int r = 0; r < 2; r++) {
                int mr = mrow + r * 8;
                if (mr >= M) continue;
                size_t idx = (size_t)mr * Nn + ncol;
                float v0 = acc[i][j][r * 2 + 0] * WINV + bv0;
                float v1 = acc[i][j][r * 2 + 1] * WINV + bv1;
                if (addend) { v0 += addend[idx]; v1 += addend[idx + 1]; }
                C[idx]     = v0;
                C[idx + 1] = v1;
                if (Ch) {
                    __half h0, l0, h1, l1;
                    splith(v0, h0, l0);
                    splith(v1, h1, l1);
                    Ch[idx] = h0;      Cl[idx] = l0;
                    Ch[idx + 1] = h1;  Cl[idx + 1] = l1;
                }
            }
        }
    }
}

// ---------------- LayerNorm (warp per row) with optional split outputs ----
__global__ __launch_bounds__(256)
void ln_kernel(const float* __restrict__ X, const float* __restrict__ gamma,
               const float* __restrict__ beta, float* __restrict__ Y,
               __half* __restrict__ Yh, __half* __restrict__ Yl)
{
    int idx = blockIdx.x * blockDim.x + threadIdx.x;
    int row = idx >> 5;
    int lane = idx & 31;
    if (row >= NNODE) return;

    const float4* xp = (const float4*)(X + (size_t)row * DMODEL);
    float4 v0 = xp[lane];
    float4 v1 = xp[lane + 32];

    float s = v0.x + v0.y + v0.z + v0.w + v1.x + v1.y + v1.z + v1.w;
#pragma unroll
    for (int o = 16; o; o >>= 1) s += __shfl_xor_sync(0xffffffffu, s, o);
    float mean = s * (1.f / 256.f);

    float d, q = 0.f;
    d = v0.x - mean; q += d * d;  d = v0.y - mean; q += d * d;
    d = v0.z - mean; q += d * d;  d = v0.w - mean; q += d * d;
    d = v1.x - mean; q += d * d;  d = v1.y - mean; q += d * d;
    d = v1.z - mean; q += d * d;  d = v1.w - mean; q += d * d;
#pragma unroll
    for (int o = 16; o; o >>= 1) q += __shfl_xor_sync(0xffffffffu, q, o);
    float inv = rsqrtf(q * (1.f / 256.f) + 1e-5f);

    const float4* gp = (const float4*)gamma;
    const float4* bp = (const float4*)beta;
    float4 g0 = gp[lane], g1 = gp[lane + 32];
    float4 b0 = bp[lane], b1 = bp[lane + 32];

    float o0[4], o1[4];
    o0[0] = (v0.x - mean) * inv * g0.x + b0.x;
    o0[1] = (v0.y - mean) * inv * g0.y + b0.y;
    o0[2] = (v0.z - mean) * inv * g0.z + b0.z;
    o0[3] = (v0.w - mean) * inv * g0.w + b0.w;
    o1[0] = (v1.x - mean) * inv * g1.x + b1.x;
    o1[1] = (v1.y - mean) * inv * g1.y + b1.y;
    o1[2] = (v1.z - mean) * inv * g1.z + b1.z;
    o1[3] = (v1.w - mean) * inv * g1.w + b1.w;

    float4* yp = (float4*)(Y + (size_t)row * DMODEL);
    yp[lane]      = make_float4(o0[0], o0[1], o0[2], o0[3]);
    yp[lane + 32] = make_float4(o1[0], o1[1], o1[2], o1[3]);

    if (Yh) {
        __half hbuf0[4], lbuf0[4], hbuf1[4], lbuf1[4];
#pragma unroll
        for (int k = 0; k < 4; k++) {
            splith(o0[k], hbuf0[k], lbuf0[k]);
            splith(o1[k], hbuf1[k], lbuf1[k]);
        }
        uint2* hp = (uint2*)(Yh + (size_t)row * DMODEL);
        uint2* lp = (uint2*)(Yl + (size_t)row * DMODEL);
        hp[lane]      = *(uint2*)hbuf0;
        hp[lane + 32] = *(uint2*)hbuf1;
        lp[lane]      = *(uint2*)lbuf0;
        lp[lane + 32] = *(uint2*)lbuf1;
    }
}

// ---------------- edge attention: warp/node, double-buffered K/V ----------
// QKVm rows of 1536: [Q(512) | K(512) | V(512)], per node, layout [head][elem].
__global__ __launch_bounds__(128)
void attn_kernel(const float* __restrict__ QKVm,
                 __half* __restrict__ Omh, __half* __restrict__ Oml)
{
    __shared__ float sm[4][512 + 2 * 1024];   // Q | (K0 V0) | (K1 V1)

    const int gwarp = (blockIdx.x * blockDim.x + threadIdx.x) >> 5;
    const int lane  = threadIdx.x & 31;
    const int winb  = threadIdx.x >> 5;
    if (gwarp >= NNODE) return;

    const int i = gwarp;
    const int a = lane >> 1;
    const int half = lane & 1;
    const int half2 = half * 2;

    float* Qs = &sm[winb][0];

    // load Q
    {
        const float4* qg = (const float4*)(QKVm + (size_t)i * QKV3);
        float4* qd = (float4*)Qs;
#pragma unroll
        for (int v = 0; v < 4; v++) qd[lane + 32 * v] = qg[lane + 32 * v];
    }

    float partial[32];
#pragma unroll
    for (int h = 0; h < 32; h++) partial[h] = 0.f;

    const int e0 = g_off[i];
    const int e1 = g_off[i + 1];

    float4 kr[4], vr[4];
    if (e0 < e1) {
        const float4* kg = (const float4*)(QKVm + (size_t)g_esrc[e0] * QKV3 + QKV);
        const float4* vg = kg + 128;
#pragma unroll
        for (int v = 0; v < 4; v++) { kr[v] = kg[lane + 32 * v]; vr[v] = vg[lane + 32 * v]; }
        float4* kd = (float4*)&sm[winb][512];
        float4* vd = (float4*)&sm[winb][1024];
#pragma unroll
        for (int v = 0; v < 4; v++) { kd[lane + 32 * v] = kr[v]; vd[lane + 32 * v] = vr[v]; }
    }
    __syncwarp();

    int cur = 0;
    for (int e = e0; e < e1; e++) {
        if (e + 1 < e1) {
            const float4* kg = (const float4*)(QKVm + (size_t)g_esrc[e + 1] * QKV3 + QKV);
            const float4* vg = kg + 128;
#pragma unroll
            for (int v = 0; v < 4; v++) { kr[v] = kg[lane + 32 * v]; vr[v] = vg[lane + 32 * v]; }
        }

        const float4* Ks4 = (const float4*)&sm[winb][512 + cur * 1024];
        const float4* Vs4 = Ks4 + 128;

        float acc[8];
#pragma unroll
        for (int b = 0; b < 8; b++) acc[b] = 0.f;
#pragma unroll
        for (int hh = 0; hh < 32; hh++) {
            float qa = Qs[hh * 16 + a];
            float4 k0 = Ks4[hh * 4 + half2];
            float4 k1 = Ks4[hh * 4 + half2 + 1];
            acc[0] += qa * k0.x; acc[1] += qa * k0.y;
            acc[2] += qa * k0.z; acc[3] += qa * k0.w;
            acc[4] += qa * k1.x; acc[5] += qa * k1.y;
            acc[6] += qa * k1.z; acc[7] += qa * k1.w;
        }
#pragma unroll
        for (int b = 0; b < 8; b++) acc[b] *= 0.25f;

        float mx = acc[0];
#pragma unroll
        for (int b = 1; b < 8; b++) mx = fmaxf(mx, acc[b]);
        mx = fmaxf(mx, __shfl_xor_sync(0xffffffffu, mx, 1));
        float ssum = 0.f;
#pragma unroll
        for (int b = 0; b < 8; b++) { acc[b] = __expf(acc[b] - mx); ssum += acc[b]; }
        ssum += __shfl_xor_sync(0xffffffffu, ssum, 1);
        float invs = 1.f / ssum;
#pragma unroll
        for (int b = 0; b < 8; b++) acc[b] *= invs;

#pragma unroll
        for (int hh = 0; hh < 32; hh++) {
            float4 v0 = Vs4[hh * 4 + half2];
            float4 v1 = Vs4[hh * 4 + half2 + 1];
            partial[hh] += acc[0] * v0.x + acc[1] * v0.y + acc[2] * v0.z + acc[3] * v0.w
                         + acc[4] * v1.x + acc[5] * v1.y + acc[6] * v1.z + acc[7] * v1.w;
        }

        if (e + 1 < e1) {
            float4* kd = (float4*)&sm[winb][512 + (cur ^ 1) * 1024];
            float4* vd = kd + 128;
#pragma unroll
            for (int v = 0; v < 4; v++) { kd[lane + 32 * v] = kr[v]; vd[lane + 32 * v] = vr[v]; }
        }
        __syncwarp();
        cur ^= 1;
    }

    __half* oph = Omh + (size_t)i * QKV;
    __half* opl = Oml + (size_t)i * QKV;
#pragma unroll
    for (int h = 0; h < 32; h++) {
        float tot = partial[h] + __shfl_xor_sync(0xffffffffu, partial[h], 1);
        if ((h >> 4) == half) {
            int idx = h * 16 + a;
            __half th, tl;
            splith(tot, th, tl);
            oph[idx] = th;
            opl[idx] = tl;
        }
    }
}

// ---------------- host launcher ----------------
extern "C" void kernel_launch(void* const* d_in, const int* in_sizes, int n_in,
                              void* d_out, int out_size)
{
    const float* x       = (const float*)d_in[0];
    const void*  eidx    =               d_in[1];
    const float* W_embed = (const float*)d_in[2];
    const float* Wq      = (const float*)d_in[3];
    const float* Wk      = (const float*)d_in[4];
    const float* Wv      = (const float*)d_in[5];
    const float* Wo      = (const float*)d_in[6];
    const float* bo      = (const float*)d_in[7];
    const float* Wm      = (const float*)d_in[8];
    const float* bm      = (const float*)d_in[9];
    const float* g_ln    = (const float*)d_in[10];
    const float* b_ln    = (const float*)d_in[11];
    const float* g_mlp   = (const float*)d_in[12];
    const float* b_mlp   = (const float*)d_in[13];
    float* out = (float*)d_out;

    __half *pxh, *pxl, *pWeh, *pWel, *pWfh, *pWfl, *pWoh, *pWol, *pWmh, *pWml;
    __half *phh, *phl, *pt1h, *pt1l, *pAh, *pAl;
    float *ph, *pt0, *pt1, *pQKV;
    cudaGetSymbolAddress((void**)&pxh,  g_xh);
    cudaGetSymbolAddress((void**)&pxl,  g_xl);
    cudaGetSymbolAddress((void**)&pWeh, g_Weh);
    cudaGetSymbolAddress((void**)&pWel, g_Wel);
    cudaGetSymbolAddress((void**)&pWfh, g_Wfh);
    cudaGetSymbolAddress((void**)&pWfl, g_Wfl);
    cudaGetSymbolAddress((void**)&pWoh, g_Woh);
    cudaGetSymbolAddress((void**)&pWol, g_Wol);
    cudaGetSymbolAddress((void**)&pWmh, g_Wmh);
    cudaGetSymbolAddress((void**)&pWml, g_Wml);
    cudaGetSymbolAddress((void**)&ph,   g_h);
    cudaGetSymbolAddress((void**)&phh,  g_hh);
    cudaGetSymbolAddress((void**)&phl,  g_hl);
    cudaGetSymbolAddress((void**)&pt0,  g_t0);
    cudaGetSymbolAddress((void**)&pt1,  g_t1);
    cudaGetSymbolAddress((void**)&pt1h, g_t1h);
    cudaGetSymbolAddress((void**)&pt1l, g_t1l);
    cudaGetSymbolAddress((void**)&pQKV, g_QKV);
    cudaGetSymbolAddress((void**)&pAh,  g_ath);
    cudaGetSymbolAddress((void**)&pAl,  g_atl);

    // launches 1-3: splits (x unscaled; all weights x32)
    split_pad_kernel<<<NNODE, 256>>>(x, pxh, pxl, FIN, KPAD, 1.0f);
    split_pad_kernel<<<DMODEL, 256>>>(W_embed, pWeh, pWel, FIN, KPAD, WSCALE);
    splitw_kernel<<<(WTOT + 255) / 256, 256>>>(Wq, Wk, Wv, Wo, Wm);

    // launch 4: embedding GEMM (profiler captures launch #4)
    const dim3 gEmb(DMODEL / BN, (NNODE + BM - 1) / BM);
    gemm3h<<<gEmb, 256>>>(pxh, pxl, pWeh, pWel, nullptr, nullptr,
                          ph, phh, phl, NNODE, DMODEL, KPAD);

    // CSR build
    detect_kernel<<<1, 32>>>((const unsigned int*)eidx);
    zero_cnt_kernel<<<(NNODE + 255) / 256, 256>>>();
    hist_kernel<<<(NEDGE + 255) / 256, 256>>>(eidx);
    scan_kernel<<<1, 1024>>>();
    scatter_kernel<<<(NEDGE + 255) / 256, 256>>>(eidx);

    const dim3 gF(QKV3 / BN,   (NNODE + BM - 1) / BM);   // 12 x 79
    const dim3 gD(DMODEL / BN, (NNODE + BM - 1) / BM);   // 2 x 79

    for (int l = 0; l < NLAYER; l++) {
        // fused QKV
        gemm3h<<<gF, 256>>>(phh, phl,
                            pWfh + (size_t)l * QKV3 * DMODEL,
                            pWfl + (size_t)l * QKV3 * DMODEL,
                            nullptr, nullptr, pQKV, nullptr, nullptr,
                            NNODE, QKV3, DMODEL);

        attn_kernel<<<(NNODE + 3) / 4, 128>>>(pQKV, pAh, pAl);

        // h1x = h + attn @ Wo^T + bo
        gemm3h<<<gD, 256>>>(pAh, pAl,
                            pWoh + (size_t)l * DMODEL * QKV,
                            pWol + (size_t)l * DMODEL * QKV,
                            bo + (size_t)l * DMODEL, ph,
                            pt0, nullptr, nullptr,
                            NNODE, DMODEL, QKV);
        ln_kernel<<<(NNODE * 32 + 255) / 256, 256>>>(pt0, g_ln + (size_t)l * DMODEL,
                                                     b_ln + (size_t)l * DMODEL,
                                                     pt1, pt1h, pt1l);

        // h2 = h1 + h1 @ Wm^T + bm
        gemm3h<<<gD, 256>>>(pt1h, pt1l,
                            pWmh + (size_t)l * DMODEL * DMODEL,
                            pWml + (size_t)l * DMODEL * DMODEL,
                            bm + (size_t)l * DMODEL, pt1,
                            pt0, nullptr, nullptr,
                            NNODE, DMODEL, DMODEL);
        bool last = (l == NLAYER - 1);
        ln_kernel<<<(NNODE * 32 + 255) / 256, 256>>>(pt0, g_mlp + (size_t)l * DMODEL,
                                                     b_mlp + (size_t)l * DMODEL,
                                                     last ? out : ph,
                                                     last ? nullptr : phh,
                                                     last ? nullptr : phl);
    }
}

// round 9
// speedup vs baseline: 1.7871x; 1.0080x over previous
#include <cuda_runtime.h>
#include <cuda_fp16.h>

// Problem constants
#define NNODE   10000
#define NEDGE   160000
#define FIN     3703
#define KPAD    3712     // FIN padded to multiple of 16
#define DMODEL  256
#define NHEAD   32
#define DK      16
#define QKV     512      // NHEAD*DK
#define QKV3    1536     // fused Q|K|V width
#define NLAYER  7

// GEMM tiling (fp16 3-term, double buffer)
#define BN 128
#define SROWH 24                   // 16 halves + 8 pad (48B rows, LDSM conflict-free)
#define WSCALE 32.0f
#define WINV   0.03125f

#define SQ1 (QKV*DMODEL)           // 131072 (one layer of Wq)
#define SQT (NLAYER*SQ1)           // 917504
#define SOT (NLAYER*DMODEL*QKV)    // 917504
#define SMT (NLAYER*DMODEL*DMODEL) // 458752
#define WTOT (3*SQT + SOT + SMT)

// ---------------- device scratch ----------------
__device__ __half g_xh [NNODE * KPAD];
__device__ __half g_xl [NNODE * KPAD];
__device__ __half g_Weh[DMODEL * KPAD];
__device__ __half g_Wel[DMODEL * KPAD];
__device__ __half g_Wfh[NLAYER * QKV3 * DMODEL];   // fused Wq|Wk|Wv (x32)
__device__ __half g_Wfl[NLAYER * QKV3 * DMODEL];
__device__ __half g_Woh[SOT];
__device__ __half g_Wol[SOT];
__device__ __half g_Wmh[SMT];
__device__ __half g_Wml[SMT];

__device__ float  g_h  [NNODE * DMODEL];
__device__ __half g_hh [NNODE * DMODEL];
__device__ __half g_hl [NNODE * DMODEL];
__device__ float  g_t0 [NNODE * DMODEL];
__device__ float  g_t1 [NNODE * DMODEL];
__device__ __half g_t1h[NNODE * DMODEL];
__device__ __half g_t1l[NNODE * DMODEL];
__device__ float  g_QKV[NNODE * QKV3];
__device__ __half g_ath[NNODE * QKV];
__device__ __half g_atl[NNODE * QKV];

__device__ int g_cnt [NNODE];
__device__ int g_off [NNODE + 1];
__device__ int g_cur [NNODE];
__device__ int g_esrc[NEDGE];
__device__ int g_is64;

// ---------------- fp16 two-term split ----------------
__device__ __forceinline__ void splith(float x, __half& hi, __half& lo) {
    hi = __float2half_rn(x);
    lo = __float2half_rn(x - __half2float(hi));
}

// ---------------- f32x2 packed helpers (sm_103a FFMA2) ----------------
__device__ __forceinline__ unsigned long long pack2(float lo, float hi) {
    unsigned long long r;
    asm("mov.b64 %0, {%1, %2};" : "=l"(r) : "f"(lo), "f"(hi));
    return r;
}
__device__ __forceinline__ void unpack2(unsigned long long v, float& lo, float& hi) {
    asm("mov.b64 {%0, %1}, %2;" : "=f"(lo), "=f"(hi) : "l"(v));
}
__device__ __forceinline__ void fma2(unsigned long long& d,
                                     unsigned long long a, unsigned long long b) {
    asm("fma.rn.f32x2 %0, %1, %2, %0;" : "+l"(d) : "l"(a), "l"(b));
}

// ---------------- split kernels ----------------
__global__ void split_pad_kernel(const float* __restrict__ src,
                                 __half* __restrict__ hi, __half* __restrict__ lo,
                                 int cols, int colspad, float scale) {
    int row = blockIdx.x;
    const float* s = src + (size_t)row * cols;
    __half* ph = hi + (size_t)row * colspad;
    __half* pl = lo + (size_t)row * colspad;
    for (int c = threadIdx.x; c < cols; c += blockDim.x) {
        __half h, l;
        splith(s[c] * scale, h, l);
        ph[c] = h; pl[c] = l;
    }
}

__global__ void splitw_kernel(const float* __restrict__ Wq, const float* __restrict__ Wk,
                              const float* __restrict__ Wv, const float* __restrict__ Wo,
                              const float* __restrict__ Wm) {
    int idx = blockIdx.x * blockDim.x + threadIdx.x;
    if (idx >= WTOT) return;
    float v; __half *dh, *dl;
    if (idx < SQT) {
        int l = idx / SQ1, r = idx % SQ1;
        v = Wq[idx]; int d = l * (3 * SQ1) + r;
        dh = g_Wfh + d; dl = g_Wfl + d;
    } else if (idx < 2 * SQT) {
        int i2 = idx - SQT;
        int l = i2 / SQ1, r = i2 % SQ1;
        v = Wk[i2]; int d = l * (3 * SQ1) + SQ1 + r;
        dh = g_Wfh + d; dl = g_Wfl + d;
    } else if (idx < 3 * SQT) {
        int i2 = idx - 2 * SQT;
        int l = i2 / SQ1, r = i2 % SQ1;
        v = Wv[i2]; int d = l * (3 * SQ1) + 2 * SQ1 + r;
        dh = g_Wfh + d; dl = g_Wfl + d;
    } else if (idx < 3 * SQT + SOT) {
        int i2 = idx - 3 * SQT;
        v = Wo[i2]; dh = g_Woh + i2; dl = g_Wol + i2;
    } else {
        int i2 = idx - 3 * SQT - SOT;
        v = Wm[i2]; dh = g_Wmh + i2; dl = g_Wml + i2;
    }
    __half h, l;
    splith(v * WSCALE, h, l);
    *dh = h; *dl = l;
}

// ---------------- edge index dtype detection + CSR ----------------
__global__ void detect_kernel(const unsigned int* __restrict__ w) {
    if (threadIdx.x == 0 && blockIdx.x == 0) {
        int is64 = 1;
        for (int i = 1; i < 128; i += 2)
            if (w[i] != 0u) { is64 = 0; break; }
        g_is64 = is64;
    }
}

__device__ __forceinline__ int read_edge(const void* eidx, int pos) {
    if (g_is64) return (int)(((const long long*)eidx)[pos]);
    return ((const int*)eidx)[pos];
}

__global__ void zero_cnt_kernel() {
    int i = blockIdx.x * blockDim.x + threadIdx.x;
    if (i < NNODE) g_cnt[i] = 0;
}

__global__ void hist_kernel(const void* __restrict__ eidx) {
    int e = blockIdx.x * blockDim.x + threadIdx.x;
    if (e >= NEDGE) return;
    atomicAdd(&g_cnt[read_edge(eidx, NEDGE + e)], 1);
}

__global__ void scan_kernel() {
    __shared__ int ss[1024];
    int t = threadIdx.x;
    const int CH = (NNODE + 1023) / 1024;
    int b = t * CH;
    int e = b + CH; if (e > NNODE) e = NNODE;
    int s = 0;
    for (int i = b; i < e; i++) s += g_cnt[i];
    ss[t] = s;
    __syncthreads();
    for (int o = 1; o < 1024; o <<= 1) {
        int v = (t >= o) ? ss[t - o] : 0;
        __syncthreads();
        ss[t] += v;
        __syncthreads();
    }
    int base = ss[t] - s;
    for (int i = b; i < e; i++) {
        g_off[i] = base;
        g_cur[i] = base;
        base += g_cnt[i];
    }
    if (t == 1023) g_off[NNODE] = ss[1023];
}

__global__ void scatter_kernel(const void* __restrict__ eidx) {
    int e = blockIdx.x * blockDim.x + threadIdx.x;
    if (e >= NEDGE) return;
    int d = read_edge(eidx, NEDGE + e);
    int s = read_edge(eidx, e);
    g_esrc[atomicAdd(&g_cur[d], 1)] = s;
}

// ---------------- fp16 mma + ldmatrix helpers ----------------
__device__ __forceinline__ void mma16(float* c,
                                      unsigned a0, unsigned a1, unsigned a2, unsigned a3,
                                      unsigned b0, unsigned b1) {
    asm volatile(
        "mma.sync.aligned.m16n8k16.row.col.f32.f16.f16.f32 "
        "{%0,%1,%2,%3}, {%4,%5,%6,%7}, {%8,%9}, {%0,%1,%2,%3};\n"
        : "+f"(c[0]), "+f"(c[1]), "+f"(c[2]), "+f"(c[3])
        : "r"(a0), "r"(a1), "r"(a2), "r"(a3), "r"(b0), "r"(b1));
}

__device__ __forceinline__ void ldsm4(unsigned& r0, unsigned& r1,
                                      unsigned& r2, unsigned& r3, unsigned addr) {
    asm volatile(
        "ldmatrix.sync.aligned.m8n8.x4.shared.b16 {%0,%1,%2,%3}, [%4];\n"
        : "=r"(r0), "=r"(r1), "=r"(r2), "=r"(r3) : "r"(addr));
}

// ---------------- GEMM: C = addend + bias + (A @ B^T)/32  (3xFP16) --------
// Template IT = 16-row i-tiles per warp. BM = 32*IT (IT=4 -> 128, IT=2 -> 64).
// A = Ah+Al (unscaled), B = Bh+Bl (pre-scaled x32). Terms: AhBh + AlBh + AhBl.
template<int IT>
__global__ __launch_bounds__(256, 2)
void gemm3h(const __half* __restrict__ Ah, const __half* __restrict__ Al,
            const __half* __restrict__ Bh, const __half* __restrict__ Bl,
            const float* __restrict__ bias, const float* __restrict__ addend,
            float* __restrict__ C, __half* __restrict__ Ch, __half* __restrict__ Cl,
            int M, int Nn, int K)
{
    constexpr int BMT   = IT * 32;
    constexpr int ATILE = BMT * SROWH;
    constexpr int BTILE = 128 * SROWH;
    constexpr int STAGE = 2 * ATILE + 2 * BTILE;

    __shared__ __align__(16) __half smem[2][STAGE];

    const int tid = threadIdx.x;
    const int m0 = blockIdx.y * BMT;
    const int n0 = blockIdx.x * BN;
    const int lane = tid & 31, wid = tid >> 5;
    const int wm = wid & 1, wn = wid >> 1;

    const int nkt = K >> 4;

    float acc[IT][4][4] = {};

    // global->smem load map: one uint4 (8 halves) per tile per thread
    const int lr = tid >> 1;            // row 0..127
    const int lc = (tid & 1) * 8;       // half-col 0 or 8
    const bool aLoad = (lr < BMT);
    const int mA = (m0 + lr < M) ? (m0 + lr) : (M - 1);
    const int nB = n0 + lr;             // Nn multiple of 128

    // ldmatrix per-lane offsets (bytes, within a tile)
    const int a_row = ((lane >> 3) & 1) * 8 + (lane & 7);
    const int a_col = ((lane >> 4) & 1) * 8;
    const unsigned aoffB = (unsigned)((a_row * SROWH + a_col) * 2);
    const int b_row = ((lane >> 4) & 1) * 8 + (lane & 7);
    const int b_col = ((lane >> 3) & 1) * 8;
    const unsigned boffB = (unsigned)((b_row * SROWH + b_col) * 2);

    unsigned sbase[2];
    sbase[0] = (unsigned)__cvta_generic_to_shared(&smem[0][0]);
    sbase[1] = (unsigned)__cvta_generic_to_shared(&smem[1][0]);

    uint4 vah, val, vbh, vbl;

#define LOADT(t_) do {                                                         \
        const int _k16 = (t_) << 4;                                           \
        if (aLoad) {                                                           \
            vah = *(const uint4*)(Ah + (size_t)mA * K + _k16 + lc);            \
            val = *(const uint4*)(Al + (size_t)mA * K + _k16 + lc);            \
        }                                                                      \
        vbh = *(const uint4*)(Bh + (size_t)nB * K + _k16 + lc);                \
        vbl = *(const uint4*)(Bl + (size_t)nB * K + _k16 + lc);                \
    } while (0)

#define STORET(st_) do {                                                       \
        __half* _s = smem[st_];                                                \
        if (aLoad) {                                                           \
            *(uint4*)&_s[        lr * SROWH + lc] = vah;                       \
            *(uint4*)&_s[ATILE + lr * SROWH + lc] = val;                       \
        }                                                                      \
        *(uint4*)&_s[2 * ATILE +         lr * SROWH + lc] = vbh;               \
        *(uint4*)&_s[2 * ATILE + BTILE + lr * SROWH + lc] = vbl;               \
    } while (0)

    LOADT(0);
    STORET(0);
    __syncthreads();

    for (int t = 0; t < nkt; t++) {
        const int cur = t & 1;
        if (t + 1 < nkt) LOADT(t + 1);

        const unsigned sb = sbase[cur];

        unsigned bh0[4], bh1[4], bl0[4], bl1[4];
#pragma unroll
        for (int jp = 0; jp < 2; jp++) {
            unsigned bd = sb + (unsigned)((2 * ATILE + (wn * 32 + jp * 16) * SROWH) * 2) + boffB;
            ldsm4(bh0[2 * jp], bh1[2 * jp], bh0[2 * jp + 1], bh1[2 * jp + 1], bd);
            ldsm4(bl0[2 * jp], bl1[2 * jp], bl0[2 * jp + 1], bl1[2 * jp + 1],
                  bd + (unsigned)(BTILE * 2));
        }
#pragma unroll
        for (int i = 0; i < IT; i++) {
            unsigned ad = sb + (unsigned)(((wm * (IT * 16) + i * 16) * SROWH) * 2) + aoffB;
            unsigned ah0, ah1, ah2, ah3, al0, al1, al2, al3;
            ldsm4(ah0, ah1, ah2, ah3, ad);
            ldsm4(al0, al1, al2, al3, ad + (unsigned)(ATILE * 2));
#pragma unroll
            for (int j = 0; j < 4; j++) {
                mma16(acc[i][j], ah0, ah1, ah2, ah3, bh0[j], bh1[j]);
                mma16(acc[i][j], al0, al1, al2, al3, bh0[j], bh1[j]);
                mma16(acc[i][j], ah0, ah1, ah2, ah3, bl0[j], bl1[j]);
            }
        }

        if (t + 1 < nkt) STORET(cur ^ 1);
        __syncthreads();
    }
#undef LOADT
#undef STORET

    // epilogue: rescale by 1/32 (weights were pre-scaled x32)
#pragma unroll
    for (int i = 0; i < IT; i++) {
        int mrow = m0 + wm * (IT * 16) + i * 16 + (lane >> 2);
#pragma unroll
        for (int j = 0; j < 4; j++) {
            int ncol = n0 + wn * 32 + j * 8 + (lane & 3) * 2;
            float bv0 = 0.f, bv1 = 0.f;
            if (bias) { bv0 = bias[ncol]; bv1 = bias[ncol + 1]; }
#pragma unroll
            for (int r = 0; r < 2; r++) {
                int mr = mrow + r * 8;
                if (mr >= M) continue;
                size_t idx = (size_t)mr * Nn + ncol;
                float v0 = acc[i][j][r * 2 + 0] * WINV + bv0;
                float v1 = acc[i][j][r * 2 + 1] * WINV + bv1;
                if (addend) { v0 += addend[idx]; v1 += addend[idx + 1]; }
                C[idx]     = v0;
                C[idx + 1] = v1;
                if (Ch) {
                    __half h0, l0, h1, l1;
                    splith(v0, h0, l0);
                    splith(v1, h1, l1);
                    Ch[idx] = h0;      Cl[idx] = l0;
                    Ch[idx + 1] = h1;  Cl[idx + 1] = l1;
                }
            }
        }
    }
}

// ---------------- LayerNorm (warp per row) with optional split outputs ----
__global__ __launch_bounds__(256)
void ln_kernel(const float* __restrict__ X, const float* __restrict__ gamma,
               const float* __restrict__ beta, float* __restrict__ Y,
               __half* __restrict__ Yh, __half* __restrict__ Yl)
{
    int idx = blockIdx.x * blockDim.x + threadIdx.x;
    int row = idx >> 5;
    int lane = idx & 31;
    if (row >= NNODE) return;

    const float4* xp = (const float4*)(X + (size_t)row * DMODEL);
    float4 v0 = xp[lane];
    float4 v1 = xp[lane + 32];

    float s = v0.x + v0.y + v0.z + v0.w + v1.x + v1.y + v1.z + v1.w;
#pragma unroll
    for (int o = 16; o; o >>= 1) s += __shfl_xor_sync(0xffffffffu, s, o);
    float mean = s * (1.f / 256.f);

    float d, q = 0.f;
    d = v0.x - mean; q += d * d;  d = v0.y - mean; q += d * d;
    d = v0.z - mean; q += d * d;  d = v0.w - mean; q += d * d;
    d = v1.x - mean; q += d * d;  d = v1.y - mean; q += d * d;
    d = v1.z - mean; q += d * d;  d = v1.w - mean; q += d * d;
#pragma unroll
    for (int o = 16; o; o >>= 1) q += __shfl_xor_sync(0xffffffffu, q, o);
    float inv = rsqrtf(q * (1.f / 256.f) + 1e-5f);

    const float4* gp = (const float4*)gamma;
    const float4* bp = (const float4*)beta;
    float4 g0 = gp[lane], g1 = gp[lane + 32];
    float4 b0 = bp[lane], b1 = bp[lane + 32];

    float o0[4], o1[4];
    o0[0] = (v0.x - mean) * inv * g0.x + b0.x;
    o0[1] = (v0.y - mean) * inv * g0.y + b0.y;
    o0[2] = (v0.z - mean) * inv * g0.z + b0.z;
    o0[3] = (v0.w - mean) * inv * g0.w + b0.w;
    o1[0] = (v1.x - mean) * inv * g1.x + b1.x;
    o1[1] = (v1.y - mean) * inv * g1.y + b1.y;
    o1[2] = (v1.z - mean) * inv * g1.z + b1.z;
    o1[3] = (v1.w - mean) * inv * g1.w + b1.w;

    float4* yp = (float4*)(Y + (size_t)row * DMODEL);
    yp[lane]      = make_float4(o0[0], o0[1], o0[2], o0[3]);
    yp[lane + 32] = make_float4(o1[0], o1[1], o1[2], o1[3]);

    if (Yh) {
        __half hbuf0[4], lbuf0[4], hbuf1[4], lbuf1[4];
#pragma unroll
        for (int k = 0; k < 4; k++) {
            splith(o0[k], hbuf0[k], lbuf0[k]);
            splith(o1[k], hbuf1[k], lbuf1[k]);
        }
        uint2* hp = (uint2*)(Yh + (size_t)row * DMODEL);
        uint2* lp = (uint2*)(Yl + (size_t)row * DMODEL);
        hp[lane]      = *(uint2*)hbuf0;
        hp[lane + 32] = *(uint2*)hbuf1;
        lp[lane]      = *(uint2*)lbuf0;
        lp[lane + 32] = *(uint2*)lbuf1;
    }
}

// ---------------- edge attention: warp/node, f32x2-packed math ------------
// QKVm rows of 1536: [Q(512) | K(512) | V(512)], per node, layout [head][elem].
__global__ __launch_bounds__(128)
void attn_kernel(const float* __restrict__ QKVm,
                 __half* __restrict__ Omh, __half* __restrict__ Oml)
{
    __shared__ float sm[4][512 + 2 * 1024];   // Q | (K0 V0) | (K1 V1)

    const int gwarp = (blockIdx.x * blockDim.x + threadIdx.x) >> 5;
    const int lane  = threadIdx.x & 31;
    const int winb  = threadIdx.x >> 5;
    if (gwarp >= NNODE) return;

    const int i = gwarp;
    const int a = lane >> 1;
    const int half = lane & 1;
    const int half2 = half * 2;

    float* Qs = &sm[winb][0];

    // load Q to smem, then cache qa*0.25 packed per head in registers
    {
        const float4* qg = (const float4*)(QKVm + (size_t)i * QKV3);
        float4* qd = (float4*)Qs;
#pragma unroll
        for (int v = 0; v < 4; v++) qd[lane + 32 * v] = qg[lane + 32 * v];
    }
    __syncwarp();

    unsigned long long qa2[32];
#pragma unroll
    for (int h = 0; h < 32; h++) {
        float qa = Qs[h * 16 + a] * 0.25f;   // fold 1/sqrt(DK): exact pow2
        qa2[h] = pack2(qa, qa);
    }

    unsigned long long partial2[32];
#pragma unroll
    for (int h = 0; h < 32; h++) partial2[h] = 0ull;

    const int e0 = g_off[i];
    const int e1 = g_off[i + 1];

    float4 kr[4], vr[4];
    if (e0 < e1) {
        const float4* kg = (const float4*)(QKVm + (size_t)g_esrc[e0] * QKV3 + QKV);
        const float4* vg = kg + 128;
#pragma unroll
        for (int v = 0; v < 4; v++) { kr[v] = kg[lane + 32 * v]; vr[v] = vg[lane + 32 * v]; }
        float4* kd = (float4*)&sm[winb][512];
        float4* vd = (float4*)&sm[winb][1024];
#pragma unroll
        for (int v = 0; v < 4; v++) { kd[lane + 32 * v] = kr[v]; vd[lane + 32 * v] = vr[v]; }
    }
    __syncwarp();

    int cur = 0;
    for (int e = e0; e < e1; e++) {
        if (e + 1 < e1) {
            const float4* kg = (const float4*)(QKVm + (size_t)g_esrc[e + 1] * QKV3 + QKV);
            const float4* vg = kg + 128;
#pragma unroll
            for (int v = 0; v < 4; v++) { kr[v] = kg[lane + 32 * v]; vr[v] = vg[lane + 32 * v]; }
        }

        const ulonglong2* Ks2 = (const ulonglong2*)&sm[winb][512 + cur * 1024];
        const ulonglong2* Vs2 = Ks2 + 128;

        // QK: acc2[p] = packed (alpha[2p], alpha[2p+1]) over this lane's 8 b's
        unsigned long long acc2[4] = {0ull, 0ull, 0ull, 0ull};
#pragma unroll
        for (int hh = 0; hh < 32; hh++) {
            ulonglong2 kA = Ks2[hh * 4 + half2];
            ulonglong2 kB = Ks2[hh * 4 + half2 + 1];
            fma2(acc2[0], qa2[hh], kA.x);
            fma2(acc2[1], qa2[hh], kA.y);
            fma2(acc2[2], qa2[hh], kB.x);
            fma2(acc2[3], qa2[hh], kB.y);
        }

        // softmax over 16 b's (8 local + pair lane)
        float a8[8];
        unpack2(acc2[0], a8[0], a8[1]);
        unpack2(acc2[1], a8[2], a8[3]);
        unpack2(acc2[2], a8[4], a8[5]);
        unpack2(acc2[3], a8[6], a8[7]);
        float mx = a8[0];
#pragma unroll
        for (int b = 1; b < 8; b++) mx = fmaxf(mx, a8[b]);
        mx = fmaxf(mx, __shfl_xor_sync(0xffffffffu, mx, 1));
        float ssum = 0.f;
#pragma unroll
        for (int b = 0; b < 8; b++) { a8[b] = __expf(a8[b] - mx); ssum += a8[b]; }
        ssum += __shfl_xor_sync(0xffffffffu, ssum, 1);
        float invs = 1.f / ssum;
#pragma unroll
        for (int b = 0; b < 8; b++) a8[b] *= invs;
        unsigned long long att2[4];
        att2[0] = pack2(a8[0], a8[1]);
        att2[1] = pack2(a8[2], a8[3]);
        att2[2] = pack2(a8[4], a8[5]);
        att2[3] = pack2(a8[6], a8[7]);

        // AV: partial2[hh] accumulates (even-b sum, odd-b sum)
#pragma unroll
        for (int hh = 0; hh < 32; hh++) {
            ulonglong2 vA = Vs2[hh * 4 + half2];
            ulonglong2 vB = Vs2[hh * 4 + half2 + 1];
            fma2(partial2[hh], att2[0], vA.x);
            fma2(partial2[hh], att2[1], vA.y);
            fma2(partial2[hh], att2[2], vB.x);
            fma2(partial2[hh], att2[3], vB.y);
        }

        if (e + 1 < e1) {
            float4* kd = (float4*)&sm[winb][512 + (cur ^ 1) * 1024];
            float4* vd = kd + 128;
#pragma unroll
            for (int v = 0; v < 4; v++) { kd[lane + 32 * v] = kr[v]; vd[lane + 32 * v] = vr[v]; }
        }
        __syncwarp();
        cur ^= 1;
    }

    __half* oph = Omh + (size_t)i * QKV;
    __half* opl = Oml + (size_t)i * QKV;
#pragma unroll
    for (int h = 0; h < 32; h++) {
        float pe, po;
        unpack2(partial2[h], pe, po);
        float tot = pe + po;
        tot += __shfl_xor_sync(0xffffffffu, tot, 1);
        if ((h >> 4) == half) {
            int idx = h * 16 + a;
            __half th, tl;
            splith(tot, th, tl);
            oph[idx] = th;
            opl[idx] = tl;
        }
    }
}

// ---------------- host launcher ----------------
extern "C" void kernel_launch(void* const* d_in, const int* in_sizes, int n_in,
                              void* d_out, int out_size)
{
    const float* x       = (const float*)d_in[0];
    const void*  eidx    =               d_in[1];
    const float* W_embed = (const float*)d_in[2];
    const float* Wq      = (const float*)d_in[3];
    const float* Wk      = (const float*)d_in[4];
    const float* Wv      = (const float*)d_in[5];
    const float* Wo      = (const float*)d_in[6];
    const float* bo      = (const float*)d_in[7];
    const float* Wm      = (const float*)d_in[8];
    const float* bm      = (const float*)d_in[9];
    const float* g_ln    = (const float*)d_in[10];
    const float* b_ln    = (const float*)d_in[11];
    const float* g_mlp   = (const float*)d_in[12];
    const float* b_mlp   = (const float*)d_in[13];
    float* out = (float*)d_out;

    __half *pxh, *pxl, *pWeh, *pWel, *pWfh, *pWfl, *pWoh, *pWol, *pWmh, *pWml;
    __half *phh, *phl, *pt1h, *pt1l, *pAh, *pAl;
    float *ph, *pt0, *pt1, *pQKV;
    cudaGetSymbolAddress((void**)&pxh,  g_xh);
    cudaGetSymbolAddress((void**)&pxl,  g_xl);
    cudaGetSymbolAddress((void**)&pWeh, g_Weh);
    cudaGetSymbolAddress((void**)&pWel, g_Wel);
    cudaGetSymbolAddress((void**)&pWfh, g_Wfh);
    cudaGetSymbolAddress((void**)&pWfl, g_Wfl);
    cudaGetSymbolAddress((void**)&pWoh, g_Woh);
    cudaGetSymbolAddress((void**)&pWol, g_Wol);
    cudaGetSymbolAddress((void**)&pWmh, g_Wmh);
    cudaGetSymbolAddress((void**)&pWml, g_Wml);
    cudaGetSymbolAddress((void**)&ph,   g_h);
    cudaGetSymbolAddress((void**)&phh,  g_hh);
    cudaGetSymbolAddress((void**)&phl,  g_hl);
    cudaGetSymbolAddress((void**)&pt0,  g_t0);
    cudaGetSymbolAddress((void**)&pt1,  g_t1);
    cudaGetSymbolAddress((void**)&pt1h, g_t1h);
    cudaGetSymbolAddress((void**)&pt1l, g_t1l);
    cudaGetSymbolAddress((void**)&pQKV, g_QKV);
    cudaGetSymbolAddress((void**)&pAh,  g_ath);
    cudaGetSymbolAddress((void**)&pAl,  g_atl);

    // launches 1-3: splits (x unscaled; all weights x32)
    split_pad_kernel<<<NNODE, 256>>>(x, pxh, pxl, FIN, KPAD, 1.0f);
    split_pad_kernel<<<DMODEL, 256>>>(W_embed, pWeh, pWel, FIN, KPAD, WSCALE);
    splitw_kernel<<<(WTOT + 255) / 256, 256>>>(Wq, Wk, Wv, Wo, Wm);

    // launch 4: embedding GEMM, IT=2 (BM=64) for occupancy; profiler slot #4
    const dim3 gEmb(DMODEL / BN, (NNODE + 63) / 64);     // 2 x 157
    gemm3h<2><<<gEmb, 256>>>(pxh, pxl, pWeh, pWel, nullptr, nullptr,
                             ph, phh, phl, NNODE, DMODEL, KPAD);

    // CSR build
    detect_kernel<<<1, 32>>>((const unsigned int*)eidx);
    zero_cnt_kernel<<<(NNODE + 255) / 256, 256>>>();
    hist_kernel<<<(NEDGE + 255) / 256, 256>>>(eidx);
    scan_kernel<<<1, 1024>>>();
    scatter_kernel<<<(NEDGE + 255) / 256, 256>>>(eidx);

    const dim3 gF(QKV3 / BN,   (NNODE + 127) / 128);     // 12 x 79
    const dim3 gD(DMODEL / BN, (NNODE + 127) / 128);     // 2 x 79

    for (int l = 0; l < NLAYER; l++) {
        // fused QKV
        gemm3h<4><<<gF, 256>>>(phh, phl,
                               pWfh + (size_t)l * QKV3 * DMODEL,
                               pWfl + (size_t)l * QKV3 * DMODEL,
                               nullptr, nullptr, pQKV, nullptr, nullptr,
                               NNODE, QKV3, DMODEL);

        attn_kernel<<<(NNODE + 3) / 4, 128>>>(pQKV, pAh, pAl);

        // h1x = h + attn @ Wo^T + bo
        gemm3h<4><<<gD, 256>>>(pAh, pAl,
                               pWoh + (size_t)l * DMODEL * QKV,
                               pWol + (size_t)l * DMODEL * QKV,
                               bo + (size_t)l * DMODEL, ph,
                               pt0, nullptr, nullptr,
                               NNODE, DMODEL, QKV);
        ln_kernel<<<(NNODE * 32 + 255) / 256, 256>>>(pt0, g_ln + (size_t)l * DMODEL,
                                                     b_ln + (size_t)l * DMODEL,
                                                     pt1, pt1h, pt1l);

        // h2 = h1 + h1 @ Wm^T + bm
        gemm3h<4><<<gD, 256>>>(pt1h, pt1l,
                               pWmh + (size_t)l * DMODEL * DMODEL,
                               pWml + (size_t)l * DMODEL * DMODEL,
                               bm + (size_t)l * DMODEL, pt1,
                               pt0, nullptr, nullptr,
                               NNODE, DMODEL, DMODEL);
        bool last = (l == NLAYER - 1);
        ln_kernel<<<(NNODE * 32 + 255) / 256, 256>>>(pt0, g_mlp + (size_t)l * DMODEL,
                                                     b_mlp + (size_t)l * DMODEL,
                                                     last ? out : ph,
                                                     last ? nullptr : phh,
                                                     last ? nullptr : phl);
    }
}

// round 10
// speedup vs baseline: 1.8212x; 1.0190x over previous
#include <cuda_runtime.h>
#include <cuda_fp16.h>

// Problem constants
#define NNODE   10000
#define NEDGE   160000
#define FIN     3703
#define KPAD    3712     // FIN padded to multiple of 16
#define DMODEL  256
#define NHEAD   32
#define DK      16
#define QKV     512      // NHEAD*DK
#define QKV3    1536     // fused Q|K|V width
#define NLAYER  7

// GEMM tiling (fp16 3-term, double buffer)
#define BN 128
#define SROWH 24                   // 16 halves + 8 pad (48B rows, LDSM conflict-free)
#define WSCALE 32.0f
#define WINV   0.03125f

#define SQ1 (QKV*DMODEL)           // 131072 (one layer of Wq)
#define SQT (NLAYER*SQ1)           // 917504
#define SOT (NLAYER*DMODEL*QKV)    // 917504
#define SMT (NLAYER*DMODEL*DMODEL) // 458752
#define WTOT (3*SQT + SOT + SMT)

// ---------------- device scratch ----------------
__device__ __half g_xh [NNODE * KPAD];
__device__ __half g_xl [NNODE * KPAD];
__device__ __half g_Weh[DMODEL * KPAD];
__device__ __half g_Wel[DMODEL * KPAD];
__device__ __half g_Wfh[NLAYER * QKV3 * DMODEL];   // fused Wq|Wk|Wv (x32)
__device__ __half g_Wfl[NLAYER * QKV3 * DMODEL];
__device__ __half g_Woh[SOT];
__device__ __half g_Wol[SOT];
__device__ __half g_Wmh[SMT];
__device__ __half g_Wml[SMT];

__device__ float  g_h  [NNODE * DMODEL];
__device__ __half g_hh [NNODE * DMODEL];
__device__ __half g_hl [NNODE * DMODEL];
__device__ float  g_t0 [NNODE * DMODEL];
__device__ float  g_t1 [NNODE * DMODEL];
__device__ __half g_t1h[NNODE * DMODEL];
__device__ __half g_t1l[NNODE * DMODEL];
__device__ float  g_QKV[NNODE * QKV3];
__device__ __half g_ath[NNODE * QKV];
__device__ __half g_atl[NNODE * QKV];

__device__ int g_cnt [NNODE];
__device__ int g_off [NNODE + 1];
__device__ int g_cur [NNODE];
__device__ int g_esrc[NEDGE];
__device__ int g_is64;

// ---------------- fp16 two-term split ----------------
__device__ __forceinline__ void splith(float x, __half& hi, __half& lo) {
    hi = __float2half_rn(x);
    lo = __float2half_rn(x - __half2float(hi));
}

// ---------------- f32x2 packed helpers (sm_103a FFMA2) ----------------
__device__ __forceinline__ unsigned long long pack2(float lo, float hi) {
    unsigned long long r;
    asm("mov.b64 %0, {%1, %2};" : "=l"(r) : "f"(lo), "f"(hi));
    return r;
}
__device__ __forceinline__ void unpack2(unsigned long long v, float& lo, float& hi) {
    asm("mov.b64 {%0, %1}, %2;" : "=f"(lo), "=f"(hi) : "l"(v));
}
__device__ __forceinline__ void fma2(unsigned long long& d,
                                     unsigned long long a, unsigned long long b) {
    asm("fma.rn.f32x2 %0, %1, %2, %0;" : "+l"(d) : "l"(a), "l"(b));
}
__device__ __forceinline__ unsigned long long add2(unsigned long long a,
                                                   unsigned long long b) {
    unsigned long long r;
    asm("add.rn.f32x2 %0, %1, %2;" : "=l"(r) : "l"(a), "l"(b));
    return r;
}

// ---------------- split kernels ----------------
__global__ void split_pad_kernel(const float* __restrict__ src,
                                 __half* __restrict__ hi, __half* __restrict__ lo,
                                 int cols, int colspad, float scale) {
    int row = blockIdx.x;
    const float* s = src + (size_t)row * cols;
    __half* ph = hi + (size_t)row * colspad;
    __half* pl = lo + (size_t)row * colspad;
    for (int c = threadIdx.x; c < cols; c += blockDim.x) {
        __half h, l;
        splith(s[c] * scale, h, l);
        ph[c] = h; pl[c] = l;
    }
}

__global__ void splitw_kernel(const float* __restrict__ Wq, const float* __restrict__ Wk,
                              const float* __restrict__ Wv, const float* __restrict__ Wo,
                              const float* __restrict__ Wm) {
    int idx = blockIdx.x * blockDim.x + threadIdx.x;
    if (idx >= WTOT) return;
    float v; __half *dh, *dl;
    if (idx < SQT) {
        int l = idx / SQ1, r = idx % SQ1;
        v = Wq[idx]; int d = l * (3 * SQ1) + r;
        dh = g_Wfh + d; dl = g_Wfl + d;
    } else if (idx < 2 * SQT) {
        int i2 = idx - SQT;
        int l = i2 / SQ1, r = i2 % SQ1;
        v = Wk[i2]; int d = l * (3 * SQ1) + SQ1 + r;
        dh = g_Wfh + d; dl = g_Wfl + d;
    } else if (idx < 3 * SQT) {
        int i2 = idx - 2 * SQT;
        int l = i2 / SQ1, r = i2 % SQ1;
        v = Wv[i2]; int d = l * (3 * SQ1) + 2 * SQ1 + r;
        dh = g_Wfh + d; dl = g_Wfl + d;
    } else if (idx < 3 * SQT + SOT) {
        int i2 = idx - 3 * SQT;
        v = Wo[i2]; dh = g_Woh + i2; dl = g_Wol + i2;
    } else {
        int i2 = idx - 3 * SQT - SOT;
        v = Wm[i2]; dh = g_Wmh + i2; dl = g_Wml + i2;
    }
    __half h, l;
    splith(v * WSCALE, h, l);
    *dh = h; *dl = l;
}

// ---------------- edge index dtype detection + CSR ----------------
__global__ void detect_kernel(const unsigned int* __restrict__ w) {
    if (threadIdx.x == 0 && blockIdx.x == 0) {
        int is64 = 1;
        for (int i = 1; i < 128; i += 2)
            if (w[i] != 0u) { is64 = 0; break; }
        g_is64 = is64;
    }
}

__device__ __forceinline__ int read_edge(const void* eidx, int pos) {
    if (g_is64) return (int)(((const long long*)eidx)[pos]);
    return ((const int*)eidx)[pos];
}

__global__ void zero_cnt_kernel() {
    int i = blockIdx.x * blockDim.x + threadIdx.x;
    if (i < NNODE) g_cnt[i] = 0;
}

__global__ void hist_kernel(const void* __restrict__ eidx) {
    int e = blockIdx.x * blockDim.x + threadIdx.x;
    if (e >= NEDGE) return;
    atomicAdd(&g_cnt[read_edge(eidx, NEDGE + e)], 1);
}

__global__ void scan_kernel() {
    __shared__ int ss[1024];
    int t = threadIdx.x;
    const int CH = (NNODE + 1023) / 1024;
    int b = t * CH;
    int e = b + CH; if (e > NNODE) e = NNODE;
    int s = 0;
    for (int i = b; i < e; i++) s += g_cnt[i];
    ss[t] = s;
    __syncthreads();
    for (int o = 1; o < 1024; o <<= 1) {
        int v = (t >= o) ? ss[t - o] : 0;
        __syncthreads();
        ss[t] += v;
        __syncthreads();
    }
    int base = ss[t] - s;
    for (int i = b; i < e; i++) {
        g_off[i] = base;
        g_cur[i] = base;
        base += g_cnt[i];
    }
    if (t == 1023) g_off[NNODE] = ss[1023];
}

__global__ void scatter_kernel(const void* __restrict__ eidx) {
    int e = blockIdx.x * blockDim.x + threadIdx.x;
    if (e >= NEDGE) return;
    int d = read_edge(eidx, NEDGE + e);
    int s = read_edge(eidx, e);
    g_esrc[atomicAdd(&g_cur[d], 1)] = s;
}

// ---------------- fp16 mma + ldmatrix helpers ----------------
__device__ __forceinline__ void mma16(float* c,
                                      unsigned a0, unsigned a1, unsigned a2, unsigned a3,
                                      unsigned b0, unsigned b1) {
    asm volatile(
        "mma.sync.aligned.m16n8k16.row.col.f32.f16.f16.f32 "
        "{%0,%1,%2,%3}, {%4,%5,%6,%7}, {%8,%9}, {%0,%1,%2,%3};\n"
        : "+f"(c[0]), "+f"(c[1]), "+f"(c[2]), "+f"(c[3])
        : "r"(a0), "r"(a1), "r"(a2), "r"(a3), "r"(b0), "r"(b1));
}

__device__ __forceinline__ void ldsm4(unsigned& r0, unsigned& r1,
                                      unsigned& r2, unsigned& r3, unsigned addr) {
    asm volatile(
        "ldmatrix.sync.aligned.m8n8.x4.shared.b16 {%0,%1,%2,%3}, [%4];\n"
        : "=r"(r0), "=r"(r1), "=r"(r2), "=r"(r3) : "r"(addr));
}

// ---------------- GEMM: C = addend + bias + (A @ B^T)/32  (3xFP16) --------
// Template IT = 16-row i-tiles per warp. BM = 32*IT.
template<int IT>
__global__ __launch_bounds__(256, 2)
void gemm3h(const __half* __restrict__ Ah, const __half* __restrict__ Al,
            const __half* __restrict__ Bh, const __half* __restrict__ Bl,
            const float* __restrict__ bias, const float* __restrict__ addend,
            float* __restrict__ C, __half* __restrict__ Ch, __half* __restrict__ Cl,
            int M, int Nn, int K)
{
    constexpr int BMT   = IT * 32;
    constexpr int ATILE = BMT * SROWH;
    constexpr int BTILE = 128 * SROWH;
    constexpr int STAGE = 2 * ATILE + 2 * BTILE;

    __shared__ __align__(16) __half smem[2][STAGE];

    const int tid = threadIdx.x;
    const int m0 = blockIdx.y * BMT;
    const int n0 = blockIdx.x * BN;
    const int lane = tid & 31, wid = tid >> 5;
    const int wm = wid & 1, wn = wid >> 1;

    const int nkt = K >> 4;

    float acc[IT][4][4] = {};

    const int lr = tid >> 1;
    const int lc = (tid & 1) * 8;
    const bool aLoad = (lr < BMT);
    const int mA = (m0 + lr < M) ? (m0 + lr) : (M - 1);
    const int nB = n0 + lr;

    const int a_row = ((lane >> 3) & 1) * 8 + (lane & 7);
    const int a_col = ((lane >> 4) & 1) * 8;
    const unsigned aoffB = (unsigned)((a_row * SROWH + a_col) * 2);
    const int b_row = ((lane >> 4) & 1) * 8 + (lane & 7);
    const int b_col = ((lane >> 3) & 1) * 8;
    const unsigned boffB = (unsigned)((b_row * SROWH + b_col) * 2);

    unsigned sbase[2];
    sbase[0] = (unsigned)__cvta_generic_to_shared(&smem[0][0]);
    sbase[1] = (unsigned)__cvta_generic_to_shared(&smem[1][0]);

    uint4 vah, val, vbh, vbl;

#define LOADT(t_) do {                                                         \
        const int _k16 = (t_) << 4;                                           \
        if (aLoad) {                                                           \
            vah = *(const uint4*)(Ah + (size_t)mA * K + _k16 + lc);            \
            val = *(const uint4*)(Al + (size_t)mA * K + _k16 + lc);            \
        }                                                                      \
        vbh = *(const uint4*)(Bh + (size_t)nB * K + _k16 + lc);                \
        vbl = *(const uint4*)(Bl + (size_t)nB * K + _k16 + lc);                \
    } while (0)

#define STORET(st_) do {                                                       \
        __half* _s = smem[st_];                                                \
        if (aLoad) {                                                           \
            *(uint4*)&_s[        lr * SROWH + lc] = vah;                       \
            *(uint4*)&_s[ATILE + lr * SROWH + lc] = val;                       \
        }                                                                      \
        *(uint4*)&_s[2 * ATILE +         lr * SROWH + lc] = vbh;               \
        *(uint4*)&_s[2 * ATILE + BTILE + lr * SROWH + lc] = vbl;               \
    } while (0)

    LOADT(0);
    STORET(0);
    __syncthreads();

    for (int t = 0; t < nkt; t++) {
        const int cur = t & 1;
        if (t + 1 < nkt) LOADT(t + 1);

        const unsigned sb = sbase[cur];

        unsigned bh0[4], bh1[4], bl0[4], bl1[4];
#pragma unroll
        for (int jp = 0; jp < 2; jp++) {
            unsigned bd = sb + (unsigned)((2 * ATILE + (wn * 32 + jp * 16) * SROWH) * 2) + boffB;
            ldsm4(bh0[2 * jp], bh1[2 * jp], bh0[2 * jp + 1], bh1[2 * jp + 1], bd);
            ldsm4(bl0[2 * jp], bl1[2 * jp], bl0[2 * jp + 1], bl1[2 * jp + 1],
                  bd + (unsigned)(BTILE * 2));
        }
#pragma unroll
        for (int i = 0; i < IT; i++) {
            unsigned ad = sb + (unsigned)(((wm * (IT * 16) + i * 16) * SROWH) * 2) + aoffB;
            unsigned ah0, ah1, ah2, ah3, al0, al1, al2, al3;
            ldsm4(ah0, ah1, ah2, ah3, ad);
            ldsm4(al0, al1, al2, al3, ad + (unsigned)(ATILE * 2));
#pragma unroll
            for (int j = 0; j < 4; j++) {
                mma16(acc[i][j], ah0, ah1, ah2, ah3, bh0[j], bh1[j]);
                mma16(acc[i][j], al0, al1, al2, al3, bh0[j], bh1[j]);
                mma16(acc[i][j], ah0, ah1, ah2, ah3, bl0[j], bl1[j]);
            }
        }

        if (t + 1 < nkt) STORET(cur ^ 1);
        __syncthreads();
    }
#undef LOADT
#undef STORET

    // epilogue: rescale by 1/32
#pragma unroll
    for (int i = 0; i < IT; i++) {
        int mrow = m0 + wm * (IT * 16) + i * 16 + (lane >> 2);
#pragma unroll
        for (int j = 0; j < 4; j++) {
            int ncol = n0 + wn * 32 + j * 8 + (lane & 3) * 2;
            float bv0 = 0.f, bv1 = 0.f;
            if (bias) { bv0 = bias[ncol]; bv1 = bias[ncol + 1]; }
#pragma unroll
            for (int r = 0; r < 2; r++) {
                int mr = mrow + r * 8;
                if (mr >= M) continue;
                size_t idx = (size_t)mr * Nn + ncol;
                float v0 = acc[i][j][r * 2 + 0] * WINV + bv0;
                float v1 = acc[i][j][r * 2 + 1] * WINV + bv1;
                if (addend) { v0 += addend[idx]; v1 += addend[idx + 1]; }
                C[idx]     = v0;
                C[idx + 1] = v1;
                if (Ch) {
                    __half h0, l0, h1, l1;
                    splith(v0, h0, l0);
                    splith(v1, h1, l1);
                    Ch[idx] = h0;      Cl[idx] = l0;
                    Ch[idx + 1] = h1;  Cl[idx + 1] = l1;
                }
            }
        }
    }
}

// ---------------- LayerNorm (warp per row) with optional split outputs ----
__global__ __launch_bounds__(256)
void ln_kernel(const float* __restrict__ X, const float* __restrict__ gamma,
               const float* __restrict__ beta, float* __restrict__ Y,
               __half* __restrict__ Yh, __half* __restrict__ Yl)
{
    int idx = blockIdx.x * blockDim.x + threadIdx.x;
    int row = idx >> 5;
    int lane = idx & 31;
    if (row >= NNODE) return;

    const float4* xp = (const float4*)(X + (size_t)row * DMODEL);
    float4 v0 = xp[lane];
    float4 v1 = xp[lane + 32];

    float s = v0.x + v0.y + v0.z + v0.w + v1.x + v1.y + v1.z + v1.w;
#pragma unroll
    for (int o = 16; o; o >>= 1) s += __shfl_xor_sync(0xffffffffu, s, o);
    float mean = s * (1.f / 256.f);

    float d, q = 0.f;
    d = v0.x - mean; q += d * d;  d = v0.y - mean; q += d * d;
    d = v0.z - mean; q += d * d;  d = v0.w - mean; q += d * d;
    d = v1.x - mean; q += d * d;  d = v1.y - mean; q += d * d;
    d = v1.z - mean; q += d * d;  d = v1.w - mean; q += d * d;
#pragma unroll
    for (int o = 16; o; o >>= 1) q += __shfl_xor_sync(0xffffffffu, q, o);
    float inv = rsqrtf(q * (1.f / 256.f) + 1e-5f);

    const float4* gp = (const float4*)gamma;
    const float4* bp = (const float4*)beta;
    float4 g0 = gp[lane], g1 = gp[lane + 32];
    float4 b0 = bp[lane], b1 = bp[lane + 32];

    float o0[4], o1[4];
    o0[0] = (v0.x - mean) * inv * g0.x + b0.x;
    o0[1] = (v0.y - mean) * inv * g0.y + b0.y;
    o0[2] = (v0.z - mean) * inv * g0.z + b0.z;
    o0[3] = (v0.w - mean) * inv * g0.w + b0.w;
    o1[0] = (v1.x - mean) * inv * g1.x + b1.x;
    o1[1] = (v1.y - mean) * inv * g1.y + b1.y;
    o1[2] = (v1.z - mean) * inv * g1.z + b1.z;
    o1[3] = (v1.w - mean) * inv * g1.w + b1.w;

    float4* yp = (float4*)(Y + (size_t)row * DMODEL);
    yp[lane]      = make_float4(o0[0], o0[1], o0[2], o0[3]);
    yp[lane + 32] = make_float4(o1[0], o1[1], o1[2], o1[3]);

    if (Yh) {
        __half hbuf0[4], lbuf0[4], hbuf1[4], lbuf1[4];
#pragma unroll
        for (int k = 0; k < 4; k++) {
            splith(o0[k], hbuf0[k], lbuf0[k]);
            splith(o1[k], hbuf1[k], lbuf1[k]);
        }
        uint2* hp = (uint2*)(Yh + (size_t)row * DMODEL);
        uint2* lp = (uint2*)(Yl + (size_t)row * DMODEL);
        hp[lane]      = *(uint2*)hbuf0;
        hp[lane + 32] = *(uint2*)hbuf1;
        lp[lane]      = *(uint2*)lbuf0;
        lp[lane + 32] = *(uint2*)lbuf1;
    }
}

// ---------------- edge attention: warp/node, f32x2, Q packed in smem -----
// QKVm rows of 1536: [Q(512) | K(512) | V(512)], per node, layout [head][elem].
__global__ __launch_bounds__(128)
void attn_kernel(const float* __restrict__ QKVm,
                 __half* __restrict__ Omh, __half* __restrict__ Oml)
{
    __shared__ unsigned long long Qd[4][512];     // (qa/4, qa/4) per (h*16+a): 16KB
    __shared__ float KVs[4][2][1024];             // double-buffered K|V: 32KB

    const int gwarp = (blockIdx.x * blockDim.x + threadIdx.x) >> 5;
    const int lane  = threadIdx.x & 31;
    const int winb  = threadIdx.x >> 5;
    if (gwarp >= NNODE) return;

    const int i = gwarp;
    const int a = lane >> 1;
    const int half = lane & 1;
    const int half2 = half * 2;

    // build packed-Q table from global Q (once per node)
    {
        const float4* qg = (const float4*)(QKVm + (size_t)i * QKV3);
#pragma unroll
        for (int v = 0; v < 4; v++) {
            float4 q = qg[lane + 32 * v];
            int e = (lane + 32 * v) * 4;
            ulonglong2* d = (ulonglong2*)&Qd[winb][e];
            float x0 = q.x * 0.25f, x1 = q.y * 0.25f;
            float x2 = q.z * 0.25f, x3 = q.w * 0.25f;
            d[0] = make_ulonglong2(pack2(x0, x0), pack2(x1, x1));
            d[1] = make_ulonglong2(pack2(x2, x2), pack2(x3, x3));
        }
    }

    unsigned long long partial2[32];
#pragma unroll
    for (int h = 0; h < 32; h++) partial2[h] = 0ull;

    const int e0 = g_off[i];
    const int e1 = g_off[i + 1];

    float4 kr[4], vr[4];
    if (e0 < e1) {
        const float4* kg = (const float4*)(QKVm + (size_t)g_esrc[e0] * QKV3 + QKV);
        const float4* vg = kg + 128;
#pragma unroll
        for (int v = 0; v < 4; v++) { kr[v] = kg[lane + 32 * v]; vr[v] = vg[lane + 32 * v]; }
        float4* kd = (float4*)&KVs[winb][0][0];
        float4* vd = kd + 128;
#pragma unroll
        for (int v = 0; v < 4; v++) { kd[lane + 32 * v] = kr[v]; vd[lane + 32 * v] = vr[v]; }
    }
    __syncwarp();

    int cur = 0;
    for (int e = e0; e < e1; e++) {
        if (e + 1 < e1) {
            const float4* kg = (const float4*)(QKVm + (size_t)g_esrc[e + 1] * QKV3 + QKV);
            const float4* vg = kg + 128;
#pragma unroll
            for (int v = 0; v < 4; v++) { kr[v] = kg[lane + 32 * v]; vr[v] = vg[lane + 32 * v]; }
        }

        const ulonglong2* Ks2 = (const ulonglong2*)&KVs[winb][cur][0];
        const ulonglong2* Vs2 = Ks2 + 128;

        // QK with 8 accumulators (head parity split for ILP)
        unsigned long long acc2[8] = {0ull,0ull,0ull,0ull,0ull,0ull,0ull,0ull};
#pragma unroll
        for (int hh = 0; hh < 32; hh += 2) {
            unsigned long long q0 = Qd[winb][hh * 16 + a];
            unsigned long long q1 = Qd[winb][(hh + 1) * 16 + a];
            ulonglong2 kA0 = Ks2[hh * 4 + half2];
            ulonglong2 kB0 = Ks2[hh * 4 + half2 + 1];
            ulonglong2 kA1 = Ks2[(hh + 1) * 4 + half2];
            ulonglong2 kB1 = Ks2[(hh + 1) * 4 + half2 + 1];
            fma2(acc2[0], q0, kA0.x); fma2(acc2[1], q0, kA0.y);
            fma2(acc2[2], q0, kB0.x); fma2(acc2[3], q0, kB0.y);
            fma2(acc2[4], q1, kA1.x); fma2(acc2[5], q1, kA1.y);
            fma2(acc2[6], q1, kB1.x); fma2(acc2[7], q1, kB1.y);
        }
        acc2[0] = add2(acc2[0], acc2[4]);
        acc2[1] = add2(acc2[1], acc2[5]);
        acc2[2] = add2(acc2[2], acc2[6]);
        acc2[3] = add2(acc2[3], acc2[7]);

        // softmax over 16 b's (8 local + pair lane)
        float a8[8];
        unpack2(acc2[0], a8[0], a8[1]);
        unpack2(acc2[1], a8[2], a8[3]);
        unpack2(acc2[2], a8[4], a8[5]);
        unpack2(acc2[3], a8[6], a8[7]);
        float mx = a8[0];
#pragma unroll
        for (int b = 1; b < 8; b++) mx = fmaxf(mx, a8[b]);
        mx = fmaxf(mx, __shfl_xor_sync(0xffffffffu, mx, 1));
        float ssum = 0.f;
#pragma unroll
        for (int b = 0; b < 8; b++) { a8[b] = __expf(a8[b] - mx); ssum += a8[b]; }
        ssum += __shfl_xor_sync(0xffffffffu, ssum, 1);
        float invs = 1.f / ssum;
#pragma unroll
        for (int b = 0; b < 8; b++) a8[b] *= invs;
        unsigned long long att2[4];
        att2[0] = pack2(a8[0], a8[1]);
        att2[1] = pack2(a8[2], a8[3]);
        att2[2] = pack2(a8[4], a8[5]);
        att2[3] = pack2(a8[6], a8[7]);

        // AV: partial2[hh] accumulates (even-b sum, odd-b sum)
#pragma unroll
        for (int hh = 0; hh < 32; hh++) {
            ulonglong2 vA = Vs2[hh * 4 + half2];
            ulonglong2 vB = Vs2[hh * 4 + half2 + 1];
            fma2(partial2[hh], att2[0], vA.x);
            fma2(partial2[hh], att2[1], vA.y);
            fma2(partial2[hh], att2[2], vB.x);
            fma2(partial2[hh], att2[3], vB.y);
        }

        if (e + 1 < e1) {
            float4* kd = (float4*)&KVs[winb][cur ^ 1][0];
            float4* vd = kd + 128;
#pragma unroll
            for (int v = 0; v < 4; v++) { kd[lane + 32 * v] = kr[v]; vd[lane + 32 * v] = vr[v]; }
        }
        __syncwarp();
        cur ^= 1;
    }

    __half* oph = Omh + (size_t)i * QKV;
    __half* opl = Oml + (size_t)i * QKV;
#pragma unroll
    for (int h = 0; h < 32; h++) {
        float pe, po;
        unpack2(partial2[h], pe, po);
        float tot = pe + po;
        tot += __shfl_xor_sync(0xffffffffu, tot, 1);
        if ((h >> 4) == half) {
            int idx = h * 16 + a;
            __half th, tl;
            splith(tot, th, tl);
            oph[idx] = th;
            opl[idx] = tl;
        }
    }
}

// ---------------- host launcher ----------------
extern "C" void kernel_launch(void* const* d_in, const int* in_sizes, int n_in,
                              void* d_out, int out_size)
{
    const float* x       = (const float*)d_in[0];
    const void*  eidx    =               d_in[1];
    const float* W_embed = (const float*)d_in[2];
    const float* Wq      = (const float*)d_in[3];
    const float* Wk      = (const float*)d_in[4];
    const float* Wv      = (const float*)d_in[5];
    const float* Wo      = (const float*)d_in[6];
    const float* bo      = (const float*)d_in[7];
    const float* Wm      = (const float*)d_in[8];
    const float* bm      = (const float*)d_in[9];
    const float* g_ln    = (const float*)d_in[10];
    const float* b_ln    = (const float*)d_in[11];
    const float* g_mlp   = (const float*)d_in[12];
    const float* b_mlp   = (const float*)d_in[13];
    float* out = (float*)d_out;

    __half *pxh, *pxl, *pWeh, *pWel, *pWfh, *pWfl, *pWoh, *pWol, *pWmh, *pWml;
    __half *phh, *phl, *pt1h, *pt1l, *pAh, *pAl;
    float *ph, *pt0, *pt1, *pQKV;
    cudaGetSymbolAddress((void**)&pxh,  g_xh);
    cudaGetSymbolAddress((void**)&pxl,  g_xl);
    cudaGetSymbolAddress((void**)&pWeh, g_Weh);
    cudaGetSymbolAddress((void**)&pWel, g_Wel);
    cudaGetSymbolAddress((void**)&pWfh, g_Wfh);
    cudaGetSymbolAddress((void**)&pWfl, g_Wfl);
    cudaGetSymbolAddress((void**)&pWoh, g_Woh);
    cudaGetSymbolAddress((void**)&pWol, g_Wol);
    cudaGetSymbolAddress((void**)&pWmh, g_Wmh);
    cudaGetSymbolAddress((void**)&pWml, g_Wml);
    cudaGetSymbolAddress((void**)&ph,   g_h);
    cudaGetSymbolAddress((void**)&phh,  g_hh);
    cudaGetSymbolAddress((void**)&phl,  g_hl);
    cudaGetSymbolAddress((void**)&pt0,  g_t0);
    cudaGetSymbolAddress((void**)&pt1,  g_t1);
    cudaGetSymbolAddress((void**)&pt1h, g_t1h);
    cudaGetSymbolAddress((void**)&pt1l, g_t1l);
    cudaGetSymbolAddress((void**)&pQKV, g_QKV);
    cudaGetSymbolAddress((void**)&pAh,  g_ath);
    cudaGetSymbolAddress((void**)&pAl,  g_atl);

    // launches 1-3: splits (x unscaled; all weights x32)
    split_pad_kernel<<<NNODE, 256>>>(x, pxh, pxl, FIN, KPAD, 1.0f);
    split_pad_kernel<<<DMODEL, 256>>>(W_embed, pWeh, pWel, FIN, KPAD, WSCALE);
    splitw_kernel<<<(WTOT + 255) / 256, 256>>>(Wq, Wk, Wv, Wo, Wm);

    // launch 4: embedding GEMM, IT=4 (BM=128; measured faster than IT=2)
    const dim3 gEmb(DMODEL / BN, (NNODE + 127) / 128);   // 2 x 79
    gemm3h<4><<<gEmb, 256>>>(pxh, pxl, pWeh, pWel, nullptr, nullptr,
                             ph, phh, phl, NNODE, DMODEL, KPAD);

    // CSR build
    detect_kernel<<<1, 32>>>((const unsigned int*)eidx);
    zero_cnt_kernel<<<(NNODE + 255) / 256, 256>>>();
    hist_kernel<<<(NEDGE + 255) / 256, 256>>>(eidx);
    scan_kernel<<<1, 1024>>>();
    scatter_kernel<<<(NEDGE + 255) / 256, 256>>>(eidx);

    const dim3 gF(QKV3 / BN,   (NNODE + 127) / 128);     // 12 x 79
    const dim3 gD(DMODEL / BN, (NNODE + 127) / 128);     // 2 x 79

    for (int l = 0; l < NLAYER; l++) {
        // fused QKV
        gemm3h<4><<<gF, 256>>>(phh, phl,
                               pWfh + (size_t)l * QKV3 * DMODEL,
                               pWfl + (size_t)l * QKV3 * DMODEL,
                               nullptr, nullptr, pQKV, nullptr, nullptr,
                               NNODE, QKV3, DMODEL);

        attn_kernel<<<(NNODE + 3) / 4, 128>>>(pQKV, pAh, pAl);

        // h1x = h + attn @ Wo^T + bo
        gemm3h<4><<<gD, 256>>>(pAh, pAl,
                               pWoh + (size_t)l * DMODEL * QKV,
                               pWol + (size_t)l * DMODEL * QKV,
                               bo + (size_t)l * DMODEL, ph,
                               pt0, nullptr, nullptr,
                               NNODE, DMODEL, QKV);
        ln_kernel<<<(NNODE * 32 + 255) / 256, 256>>>(pt0, g_ln + (size_t)l * DMODEL,
                                                     b_ln + (size_t)l * DMODEL,
                                                     pt1, pt1h, pt1l);

        // h2 = h1 + h1 @ Wm^T + bm
        gemm3h<4><<<gD, 256>>>(pt1h, pt1l,
                               pWmh + (size_t)l * DMODEL * DMODEL,
                               pWml + (size_t)l * DMODEL * DMODEL,
                               bm + (size_t)l * DMODEL, pt1,
                               pt0, nullptr, nullptr,
                               NNODE, DMODEL, DMODEL);
        bool last = (l == NLAYER - 1);
        ln_kernel<<<(NNODE * 32 + 255) / 256, 256>>>(pt0, g_mlp + (size_t)l * DMODEL,
                                                     b_mlp + (size_t)l * DMODEL,
                                                     last ? out : ph,
                                                     last ? nullptr : phh,
                                                     last ? nullptr : phl);
    }
}